// round 1
// baseline (speedup 1.0000x reference)
#include <cuda_runtime.h>
#include <math.h>

// ---------------------------------------------------------------------------
// MultiScaleBlock: B=4, H=W=256, DIM=96, DIM_OUT=192, HEADS=3, hd=64, WS=8,
// pooled 128x128 output. fp32 throughout.
// ---------------------------------------------------------------------------

#define B_      4
#define H_      256
#define W_      256
#define DIM_    96
#define DOUT_   192
#define HID_    768
#define NPIX    (B_*H_*W_)          // 262144
#define NPOOL   (B_*128*128)        // 65536
#define NWIN    (B_*32*32)          // 4096

// scratch (device globals; no allocation allowed)
__device__ float g_xn  [(size_t)NPIX  * DIM_ ];   // 96MB
__device__ float g_proj[(size_t)NPIX  * DOUT_];   // 192MB
__device__ float g_qkv [(size_t)NPIX  * 576  ];   // 576MB
__device__ float g_yn  [(size_t)NPOOL * DOUT_];   // 48MB
__device__ float g_h   [(size_t)NPOOL * HID_ ];   // 192MB

// ---------------------------------------------------------------------------
// LayerNorm over 96 channels, warp per row
// ---------------------------------------------------------------------------
__global__ __launch_bounds__(256) void ln96_kernel(
    const float* __restrict__ x, const float* __restrict__ g,
    const float* __restrict__ bb, float* __restrict__ out)
{
    int row  = blockIdx.x * 8 + (threadIdx.x >> 5);
    int lane = threadIdx.x & 31;
    const float* p = x + (size_t)row * 96;
    float v0 = p[lane], v1 = p[lane+32], v2 = p[lane+64];
    float s = v0 + v1 + v2;
    #pragma unroll
    for (int o = 16; o > 0; o >>= 1) s += __shfl_xor_sync(0xffffffffu, s, o);
    float mean = s * (1.0f/96.0f);
    float d0 = v0-mean, d1 = v1-mean, d2 = v2-mean;
    float vs = d0*d0 + d1*d1 + d2*d2;
    #pragma unroll
    for (int o = 16; o > 0; o >>= 1) vs += __shfl_xor_sync(0xffffffffu, vs, o);
    float inv = rsqrtf(vs * (1.0f/96.0f) + 1e-6f);
    float* q = out + (size_t)row * 96;
    q[lane]    = d0*inv*g[lane]    + bb[lane];
    q[lane+32] = d1*inv*g[lane+32] + bb[lane+32];
    q[lane+64] = d2*inv*g[lane+64] + bb[lane+64];
}

// LayerNorm over 192 channels, warp per row
__global__ __launch_bounds__(256) void ln192_kernel(
    const float* __restrict__ x, const float* __restrict__ g,
    const float* __restrict__ bb, float* __restrict__ out)
{
    int row  = blockIdx.x * 8 + (threadIdx.x >> 5);
    int lane = threadIdx.x & 31;
    const float* p = x + (size_t)row * 192;
    float v[6];
    float s = 0.f;
    #pragma unroll
    for (int i = 0; i < 6; i++) { v[i] = p[lane + 32*i]; s += v[i]; }
    #pragma unroll
    for (int o = 16; o > 0; o >>= 1) s += __shfl_xor_sync(0xffffffffu, s, o);
    float mean = s * (1.0f/192.0f);
    float vs = 0.f;
    #pragma unroll
    for (int i = 0; i < 6; i++) { v[i] -= mean; vs += v[i]*v[i]; }
    #pragma unroll
    for (int o = 16; o > 0; o >>= 1) vs += __shfl_xor_sync(0xffffffffu, vs, o);
    float inv = rsqrtf(vs * (1.0f/192.0f) + 1e-6f);
    float* q = out + (size_t)row * 192;
    #pragma unroll
    for (int i = 0; i < 6; i++)
        q[lane + 32*i] = v[i]*inv*g[lane + 32*i] + bb[lane + 32*i];
}

// ---------------------------------------------------------------------------
// Generic SGEMM: C[M,N] = epi(A[M,K] @ W[K,N] + bias)
// BM=128 BN=64 BK=16, 256 threads, 8x4 microtile. M%128==0, N%64==0, K%16==0.
// epi: 0 = none, 1 = gelu(exact), 2 = add addsrc
// ---------------------------------------------------------------------------
__device__ __forceinline__ float gelu_exact(float v)
{
    return 0.5f * v * (1.0f + erff(v * 0.70710678118654752f));
}

__global__ __launch_bounds__(256) void gemm_kernel(
    const float* __restrict__ A, const float* __restrict__ W,
    const float* __restrict__ bias, float* __restrict__ C,
    const float* __restrict__ addsrc, int M, int N, int K, int epi)
{
    const int BM = 128, BN = 64, BK = 16;
    __shared__ float As[BK][BM];
    __shared__ float Ws[BK][BN];
    int bm = blockIdx.y * BM;
    int bn = blockIdx.x * BN;
    int tid = threadIdx.x;
    int tx = tid & 15;   // N dir, 4 cols each
    int ty = tid >> 4;   // M dir, 8 rows each

    float acc[8][4];
    #pragma unroll
    for (int i = 0; i < 8; i++)
        #pragma unroll
        for (int j = 0; j < 4; j++) acc[i][j] = 0.f;

    for (int k0 = 0; k0 < K; k0 += BK) {
        // A tile: 128x16 = 512 float4, 2 per thread (consecutive)
        #pragma unroll
        for (int q = 0; q < 2; q++) {
            int f  = tid * 2 + q;
            int r  = f >> 2;
            int cg = (f & 3) * 4;
            float4 v = *reinterpret_cast<const float4*>(&A[(size_t)(bm + r) * K + k0 + cg]);
            As[cg+0][r] = v.x; As[cg+1][r] = v.y; As[cg+2][r] = v.z; As[cg+3][r] = v.w;
        }
        // W tile: 16x64 = 256 float4, 1 per thread
        {
            int r = tid >> 4;
            int c = (tid & 15) * 4;
            float4 v = *reinterpret_cast<const float4*>(&W[(size_t)(k0 + r) * N + bn + c]);
            *reinterpret_cast<float4*>(&Ws[r][c]) = v;
        }
        __syncthreads();
        #pragma unroll
        for (int kk = 0; kk < BK; kk++) {
            float a[8], b[4];
            #pragma unroll
            for (int i = 0; i < 8; i++) a[i] = As[kk][ty*8 + i];
            #pragma unroll
            for (int j = 0; j < 4; j++) b[j] = Ws[kk][tx*4 + j];
            #pragma unroll
            for (int i = 0; i < 8; i++)
                #pragma unroll
                for (int j = 0; j < 4; j++)
                    acc[i][j] = fmaf(a[i], b[j], acc[i][j]);
        }
        __syncthreads();
    }

    float bv[4];
    #pragma unroll
    for (int j = 0; j < 4; j++) bv[j] = bias[bn + tx*4 + j];

    #pragma unroll
    for (int i = 0; i < 8; i++) {
        size_t row = (size_t)bm + ty*8 + i;
        size_t off = row * N + bn + tx*4;
        float4 r;
        r.x = acc[i][0] + bv[0];
        r.y = acc[i][1] + bv[1];
        r.z = acc[i][2] + bv[2];
        r.w = acc[i][3] + bv[3];
        if (epi == 1) {
            r.x = gelu_exact(r.x); r.y = gelu_exact(r.y);
            r.z = gelu_exact(r.z); r.w = gelu_exact(r.w);
        } else if (epi == 2) {
            float4 s = *reinterpret_cast<const float4*>(&addsrc[off]);
            r.x += s.x; r.y += s.y; r.z += s.z; r.w += s.w;
        }
        *reinterpret_cast<float4*>(&C[off]) = r;
    }
}

// ---------------------------------------------------------------------------
// 2x2 maxpool of g_proj (4,256,256,192) -> y (=d_out) (4,128,128,192)
// ---------------------------------------------------------------------------
__global__ __launch_bounds__(256) void pool_kernel(
    const float* __restrict__ p, float* __restrict__ y)
{
    int i = blockIdx.x * 256 + threadIdx.x;      // < 12582912
    int c   = i % 192;
    int pix = i / 192;
    int wp = pix & 127, hp = (pix >> 7) & 127, b = pix >> 14;
    size_t base = (((size_t)b*256 + hp*2)*256 + wp*2)*192 + c;
    const size_t rs = 256*192;
    float v = fmaxf(fmaxf(p[base], p[base+192]),
                    fmaxf(p[base+rs], p[base+rs+192]));
    y[i] = v;
}

// ---------------------------------------------------------------------------
// Per-window attention: q-pool + 3 heads softmax attention + attn_proj,
// accumulate into y (d_out). One block (256 thr) per window.
// qkv layout per pixel row: [q(3*64) | k(3*64) | v(3*64)], head h at h*64.
// ---------------------------------------------------------------------------
#define SM_QP   0                     // 16*192
#define SM_KH   (16*192)              // 64*65 (kh[d][s], padded)
#define SM_VH   (SM_KH + 64*65)       // 64*64 (vh[s][d])
#define SM_OW   (SM_VH + 64*64)       // 16*192
#define SM_SC   (SM_OW + 16*192)      // 16*64
#define SM_TOT  (SM_SC + 16*64)       // 15424 floats = 61696 bytes

__global__ __launch_bounds__(256) void attn_kernel(
    const float* __restrict__ qkv, const float* __restrict__ pw,
    const float* __restrict__ pb, float* __restrict__ y)
{
    extern __shared__ float sm[];
    float* qp = sm + SM_QP;
    float* kh = sm + SM_KH;
    float* vh = sm + SM_VH;
    float* ow = sm + SM_OW;
    float* sc = sm + SM_SC;

    int blk = blockIdx.x;
    int b = blk >> 10, wi = (blk >> 5) & 31, wj = blk & 31;
    int tid = threadIdx.x;

    // 1) pooled q: qp[t2*192 + ch] = max over 2x2 source tokens
    for (int i = tid; i < 16*192; i += 256) {
        int t2 = i / 192, ch = i % 192;
        int r2 = t2 >> 2, c2 = t2 & 3;
        float m = -1e30f;
        #pragma unroll
        for (int dr = 0; dr < 2; dr++)
            #pragma unroll
            for (int dc = 0; dc < 2; dc++) {
                int r = r2*2 + dr, c = c2*2 + dc;
                int row = ((b*256 + wi*8 + r) << 8) + wj*8 + c;
                m = fmaxf(m, qkv[(size_t)row*576 + ch]);
            }
        qp[i] = m;
    }

    for (int h = 0; h < 3; h++) {
        __syncthreads();
        // load k (transposed, padded) and v for this head
        for (int i = tid; i < 64*64; i += 256) {
            int d = i & 63, s = i >> 6;
            int row = ((b*256 + wi*8 + (s >> 3)) << 8) + wj*8 + (s & 7);
            kh[d*65 + s] = qkv[(size_t)row*576 + 192 + h*64 + d];
        }
        for (int i = tid; i < 64*64; i += 256) {
            int d = i & 63, s = i >> 6;
            int row = ((b*256 + wi*8 + (s >> 3)) << 8) + wj*8 + (s & 7);
            vh[s*64 + d] = qkv[(size_t)row*576 + 384 + h*64 + d];
        }
        __syncthreads();
        // scores[t2][s] = (qp[t2, h*64:] . k[s]) / 8
        for (int i = tid; i < 16*64; i += 256) {
            int t2 = i >> 6, s = i & 63;
            float acc = 0.f;
            #pragma unroll
            for (int d = 0; d < 64; d++)
                acc = fmaf(qp[t2*192 + h*64 + d], kh[d*65 + s], acc);
            sc[i] = acc * 0.125f;
        }
        __syncthreads();
        // softmax over 64 keys: warp per row
        {
            int warp = tid >> 5, lane = tid & 31;
            for (int t2 = warp; t2 < 16; t2 += 8) {
                float v0 = sc[t2*64 + lane], v1 = sc[t2*64 + 32 + lane];
                float mx = fmaxf(v0, v1);
                #pragma unroll
                for (int o = 16; o > 0; o >>= 1)
                    mx = fmaxf(mx, __shfl_xor_sync(0xffffffffu, mx, o));
                float e0 = expf(v0 - mx), e1 = expf(v1 - mx);
                float ss = e0 + e1;
                #pragma unroll
                for (int o = 16; o > 0; o >>= 1)
                    ss += __shfl_xor_sync(0xffffffffu, ss, o);
                float inv = 1.f / ss;
                sc[t2*64 + lane]      = e0 * inv;
                sc[t2*64 + 32 + lane] = e1 * inv;
            }
        }
        __syncthreads();
        // out[t2][h*64+d] = probs[t2] . v[:, d]
        for (int i = tid; i < 16*64; i += 256) {
            int t2 = i >> 6, d = i & 63;
            float acc = 0.f;
            #pragma unroll
            for (int s = 0; s < 64; s++)
                acc = fmaf(sc[t2*64 + s], vh[s*64 + d], acc);
            ow[t2*192 + h*64 + d] = acc;
        }
    }
    __syncthreads();
    // attn_proj (16x192 @ 192x192) + bias, accumulate into y at pooled coords
    for (int i = tid; i < 16*192; i += 256) {
        int t2 = i / 192, col = i % 192;
        float acc = pb[col];
        #pragma unroll 8
        for (int k = 0; k < 192; k++)
            acc = fmaf(ow[t2*192 + k], pw[k*192 + col], acc);
        int r2 = t2 >> 2, c2 = t2 & 3;
        size_t orow = ((size_t)(b*128 + wi*4 + r2))*128 + wj*4 + c2;
        y[orow*192 + col] += acc;
    }
}

// ---------------------------------------------------------------------------
// launch
// ---------------------------------------------------------------------------
extern "C" void kernel_launch(void* const* d_in, const int* in_sizes, int n_in,
                              void* d_out, int out_size)
{
    const float* x       = (const float*)d_in[0];
    const float* n1g     = (const float*)d_in[1];
    const float* n1b     = (const float*)d_in[2];
    const float* proj_w  = (const float*)d_in[3];
    const float* proj_b  = (const float*)d_in[4];
    const float* qkv_w   = (const float*)d_in[5];
    const float* qkv_b   = (const float*)d_in[6];
    const float* apw     = (const float*)d_in[7];
    const float* apb     = (const float*)d_in[8];
    const float* n2g     = (const float*)d_in[9];
    const float* n2b     = (const float*)d_in[10];
    const float* w1      = (const float*)d_in[11];
    const float* b1      = (const float*)d_in[12];
    const float* w2      = (const float*)d_in[13];
    const float* b2      = (const float*)d_in[14];
    float* y = (float*)d_out;

    float *xn, *proj, *qkv, *yn, *hbuf;
    cudaGetSymbolAddress((void**)&xn,   g_xn);
    cudaGetSymbolAddress((void**)&proj, g_proj);
    cudaGetSymbolAddress((void**)&qkv,  g_qkv);
    cudaGetSymbolAddress((void**)&yn,   g_yn);
    cudaGetSymbolAddress((void**)&hbuf, g_h);

    static bool attr_done = false;
    if (!attr_done) {
        cudaFuncSetAttribute(attn_kernel,
            cudaFuncAttributeMaxDynamicSharedMemorySize, SM_TOT * 4);
        attr_done = true;
    }

    // 1) LN1: x -> xn
    ln96_kernel<<<NPIX/8, 256>>>(x, n1g, n1b, xn);
    // 2) proj GEMM: xn @ proj_w + b -> g_proj
    gemm_kernel<<<dim3(DOUT_/64, NPIX/128), 256>>>(xn, proj_w, proj_b, proj,
                                                   nullptr, NPIX, DOUT_, DIM_, 0);
    // 3) maxpool -> y (shortcut)
    pool_kernel<<<(NPOOL*DOUT_)/256, 256>>>(proj, y);
    // 4) qkv GEMM: xn @ qkv_w + b -> g_qkv
    gemm_kernel<<<dim3(576/64, NPIX/128), 256>>>(xn, qkv_w, qkv_b, qkv,
                                                 nullptr, NPIX, 576, DIM_, 0);
    // 5) windowed attention (+= into y)
    attn_kernel<<<NWIN, 256, SM_TOT * 4>>>(qkv, apw, apb, y);
    // 6) LN2: y -> yn
    ln192_kernel<<<NPOOL/8, 256>>>(y, n2g, n2b, yn);
    // 7) mlp1 GEMM with gelu: yn @ w1 + b1 -> g_h
    gemm_kernel<<<dim3(HID_/64, NPOOL/128), 256>>>(yn, w1, b1, hbuf,
                                                   nullptr, NPOOL, HID_, DOUT_, 1);
    // 8) mlp2 GEMM with residual add: y + g_h @ w2 + b2 -> d_out
    gemm_kernel<<<dim3(DOUT_/64, NPOOL/128), 256>>>(hbuf, w2, b2, y,
                                                    y, NPOOL, DOUT_, HID_, 2);
}

// round 3
// speedup vs baseline: 1.5527x; 1.5527x over previous
#include <cuda_runtime.h>
#include <cuda_bf16.h>
#include <cstdint>
#include <math.h>

// ===========================================================================
// MultiScaleBlock on GB300 (compiled as plain sm_103 PTX): bf16x3 hi/lo-split
// GEMMs on mma.sync (HMMA) + ldmatrix + cp.async. tcgen05 is unavailable
// because the harness PTX targets sm_103 (non-'a').
// ===========================================================================

#define NPIX   (4*256*256)     // 262144
#define NPOOL  (4*128*128)     // 65536
#define NWIN   (4*32*32)       // 4096

// ---------------- scratch (device globals; no allocation allowed) ----------
__device__ __nv_bfloat16 g_xh [(size_t)NPIX  * 96];
__device__ __nv_bfloat16 g_xl [(size_t)NPIX  * 96];
__device__ float         g_proj[(size_t)NPIX * 192];
__device__ float         g_qkv[(size_t)NPIX  * 576];
__device__ __nv_bfloat16 g_ynh[(size_t)NPOOL * 192];
__device__ __nv_bfloat16 g_ynl[(size_t)NPOOL * 192];
__device__ __nv_bfloat16 g_hh [(size_t)NPOOL * 768];
__device__ __nv_bfloat16 g_hl [(size_t)NPOOL * 768];
// weights converted to [N][K] bf16 hi/lo (transposed)
__device__ __nv_bfloat16 g_wph[192*96],  g_wpl[192*96];
__device__ __nv_bfloat16 g_wqh[576*96],  g_wql[576*96];
__device__ __nv_bfloat16 g_w1h[768*192], g_w1l[768*192];
__device__ __nv_bfloat16 g_w2h[192*768], g_w2l[192*768];

// ---------------- helpers ---------------------------------------------------
__device__ __forceinline__ uint32_t smem_u32(const void* p) {
    uint32_t a;
    asm("{ .reg .u64 t; cvta.to.shared.u64 t, %1; cvt.u32.u64 %0, t; }"
        : "=r"(a) : "l"(p));
    return a;
}

__device__ __forceinline__ void cp16(uint32_t s, const void* g) {
    asm volatile("cp.async.ca.shared.global [%0], [%1], 16;"
                 :: "r"(s), "l"(g) : "memory");
}
__device__ __forceinline__ void cp_commit() {
    asm volatile("cp.async.commit_group;" ::: "memory");
}
template<int N>
__device__ __forceinline__ void cp_wait() {
    asm volatile("cp.async.wait_group %0;" :: "n"(N) : "memory");
}

__device__ __forceinline__ void ldsm4(uint32_t* r, uint32_t a) {
    asm volatile("ldmatrix.sync.aligned.m8n8.x4.shared.b16 {%0,%1,%2,%3}, [%4];"
        : "=r"(r[0]), "=r"(r[1]), "=r"(r[2]), "=r"(r[3]) : "r"(a));
}

__device__ __forceinline__ void mma_bf16(float* d, const uint32_t* a,
                                         uint32_t b0, uint32_t b1) {
    asm volatile(
        "mma.sync.aligned.m16n8k16.row.col.f32.bf16.bf16.f32 "
        "{%0,%1,%2,%3}, {%4,%5,%6,%7}, {%8,%9}, {%0,%1,%2,%3};"
        : "+f"(d[0]), "+f"(d[1]), "+f"(d[2]), "+f"(d[3])
        : "r"(a[0]), "r"(a[1]), "r"(a[2]), "r"(a[3]), "r"(b0), "r"(b1));
}

__device__ __forceinline__ void split_bf16(float v, __nv_bfloat16& h, __nv_bfloat16& l) {
    h = __float2bfloat16(v);
    l = __float2bfloat16(v - __bfloat162float(h));
}

__device__ __forceinline__ float gelu_exact(float v) {
    return 0.5f * v * (1.0f + erff(v * 0.70710678118654752f));
}

// ---------------- HMMA GEMM -------------------------------------------------
// C[M,N]-tile = A[M,K] @ B[N,K]^T, bf16 hi/lo x3 products, fp32 accum.
// BM=128, BN=96, BK=32, 256 threads, warps 4x2, warp tile 32x48.
// epi: 0 = fp32 +bias; 1 = gelu -> bf16 hi/lo; 2 = +bias +addsrc fp32.
#define LDA     40                     // BK + 8 pad (half-words)
#define SA_HI   0
#define SA_LO   (128*LDA*2)            // 10240
#define SB_HI   (2*128*LDA*2)          // 20480
#define SB_LO   (SB_HI + 96*LDA*2)     // 28160
#define STAGE_B (SB_LO + 96*LDA*2)     // 35840
#define GEMM_SMEM (2*STAGE_B)          // 71680

__global__ __launch_bounds__(256, 2) void gemm_mma(
    const __nv_bfloat16* __restrict__ Ah, const __nv_bfloat16* __restrict__ Al,
    const __nv_bfloat16* __restrict__ Bh, const __nv_bfloat16* __restrict__ Bl,
    int K, int N, int epi,
    const float* __restrict__ bias,
    float* __restrict__ Cf,
    __nv_bfloat16* __restrict__ Ch, __nv_bfloat16* __restrict__ Cl,
    const float* __restrict__ addsrc)
{
    extern __shared__ char smem[];
    const uint32_t sb = smem_u32(smem);
    const int tid = threadIdx.x, lane = tid & 31, warp = tid >> 5;
    const int wm = (warp >> 1) * 32;       // warp m offset in block
    const int wn = (warp & 1) * 48;        // warp n offset in block
    const size_t bm = (size_t)blockIdx.y * 128;
    const size_t bn = (size_t)blockIdx.x * 96;
    const int C = K >> 5;

    const __nv_bfloat16* AhB = Ah + bm * K;
    const __nv_bfloat16* AlB = Al + bm * K;
    const __nv_bfloat16* BhB = Bh + bn * K;
    const __nv_bfloat16* BlB = Bl + bn * K;

    float acc[2][6][4];
    #pragma unroll
    for (int i = 0; i < 2; i++)
        #pragma unroll
        for (int j = 0; j < 6; j++)
            #pragma unroll
            for (int q = 0; q < 4; q++) acc[i][j][q] = 0.f;

    // ---- async load of one stage ----
    auto load_stage = [&](int s, int c) {
        const uint32_t st = sb + (uint32_t)s * STAGE_B;
        const size_t k0 = (size_t)c * 32;
        #pragma unroll
        for (int i = tid; i < 512; i += 256) {       // A: 128 rows x 4 chunks
            int r = i >> 2, q = i & 3;
            uint32_t d = st + (uint32_t)(r * LDA + q * 8) * 2;
            size_t go = (size_t)r * K + k0 + q * 8;
            cp16(d + SA_HI, AhB + go);
            cp16(d + SA_LO, AlB + go);
        }
        for (int i = tid; i < 384; i += 256) {       // B: 96 rows x 4 chunks
            int r = i >> 2, q = i & 3;
            uint32_t d = st + (uint32_t)(r * LDA + q * 8) * 2;
            size_t go = (size_t)r * K + k0 + q * 8;
            cp16(d + SB_HI, BhB + go);
            cp16(d + SB_LO, BlB + go);
        }
        cp_commit();
    };

    // ---- compute one stage ----
    auto compute_stage = [&](int s) {
        const uint32_t st = sb + (uint32_t)s * STAGE_B;
        #pragma unroll
        for (int k16 = 0; k16 < 2; k16++) {
            uint32_t ah[2][4], al[2][4];
            #pragma unroll
            for (int mi = 0; mi < 2; mi++) {
                int row = wm + mi * 16 + (lane & 15);
                int col = k16 * 16 + (lane >> 4) * 8;
                uint32_t ad = st + (uint32_t)(row * LDA + col) * 2;
                ldsm4(ah[mi], ad + SA_HI);
                ldsm4(al[mi], ad + SA_LO);
            }
            #pragma unroll
            for (int ng = 0; ng < 3; ng++) {
                uint32_t bh[4], bl[4];
                int nr = wn + ng * 16 + (lane & 7) + ((lane >> 4) & 1) * 8;
                int bc = k16 * 16 + ((lane >> 3) & 1) * 8;
                uint32_t bd = st + (uint32_t)(nr * LDA + bc) * 2;
                ldsm4(bh, bd + SB_HI);
                ldsm4(bl, bd + SB_LO);
                #pragma unroll
                for (int mi = 0; mi < 2; mi++) {
                    #pragma unroll
                    for (int sub = 0; sub < 2; sub++) {
                        float* d = acc[mi][ng * 2 + sub];
                        mma_bf16(d, ah[mi], bh[2*sub], bh[2*sub+1]);
                        mma_bf16(d, ah[mi], bl[2*sub], bl[2*sub+1]);
                        mma_bf16(d, al[mi], bh[2*sub], bh[2*sub+1]);
                    }
                }
            }
        }
    };

    // ---- 2-stage pipeline ----
    load_stage(0, 0);
    for (int c = 0; c < C; c++) {
        if (c + 1 < C) {
            load_stage((c + 1) & 1, c + 1);
            cp_wait<1>();
        } else {
            cp_wait<0>();
        }
        __syncthreads();
        compute_stage(c & 1);
        __syncthreads();
    }

    // ---- epilogue ----
    #pragma unroll
    for (int mi = 0; mi < 2; mi++) {
        #pragma unroll
        for (int nj = 0; nj < 6; nj++) {
            size_t row0 = bm + wm + mi * 16 + (lane >> 2);
            size_t col  = bn + wn + nj * 8 + 2 * (lane & 3);
            float b0 = bias[col], b1 = bias[col + 1];
            float v00 = acc[mi][nj][0] + b0, v01 = acc[mi][nj][1] + b1;
            float v10 = acc[mi][nj][2] + b0, v11 = acc[mi][nj][3] + b1;
            if (epi == 0) {
                float2* p0 = reinterpret_cast<float2*>(Cf + row0 * N + col);
                float2* p1 = reinterpret_cast<float2*>(Cf + (row0 + 8) * N + col);
                *p0 = make_float2(v00, v01);
                *p1 = make_float2(v10, v11);
            } else if (epi == 1) {
                v00 = gelu_exact(v00); v01 = gelu_exact(v01);
                v10 = gelu_exact(v10); v11 = gelu_exact(v11);
                __nv_bfloat16 h, l;
                __nv_bfloat162 hp, lp;
                split_bf16(v00, h, l); hp.x = h; lp.x = l;
                split_bf16(v01, h, l); hp.y = h; lp.y = l;
                *reinterpret_cast<__nv_bfloat162*>(Ch + row0 * N + col) = hp;
                *reinterpret_cast<__nv_bfloat162*>(Cl + row0 * N + col) = lp;
                split_bf16(v10, h, l); hp.x = h; lp.x = l;
                split_bf16(v11, h, l); hp.y = h; lp.y = l;
                *reinterpret_cast<__nv_bfloat162*>(Ch + (row0 + 8) * N + col) = hp;
                *reinterpret_cast<__nv_bfloat162*>(Cl + (row0 + 8) * N + col) = lp;
            } else {
                const float2 a0 = *reinterpret_cast<const float2*>(addsrc + row0 * N + col);
                const float2 a1 = *reinterpret_cast<const float2*>(addsrc + (row0 + 8) * N + col);
                float2* p0 = reinterpret_cast<float2*>(Cf + row0 * N + col);
                float2* p1 = reinterpret_cast<float2*>(Cf + (row0 + 8) * N + col);
                *p0 = make_float2(v00 + a0.x, v01 + a0.y);
                *p1 = make_float2(v10 + a1.x, v11 + a1.y);
            }
        }
    }
}

// ---------------- LayerNorm -> bf16 hi/lo ----------------------------------
__global__ __launch_bounds__(256) void ln96b_kernel(
    const float* __restrict__ x, const float* __restrict__ g,
    const float* __restrict__ bb,
    __nv_bfloat16* __restrict__ hi, __nv_bfloat16* __restrict__ lo)
{
    int row  = blockIdx.x * 8 + (threadIdx.x >> 5);
    int lane = threadIdx.x & 31;
    const float* p = x + (size_t)row * 96;
    float v0 = p[lane], v1 = p[lane+32], v2 = p[lane+64];
    float s = v0 + v1 + v2;
    #pragma unroll
    for (int o = 16; o > 0; o >>= 1) s += __shfl_xor_sync(0xffffffffu, s, o);
    float mean = s * (1.0f/96.0f);
    float d0 = v0-mean, d1 = v1-mean, d2 = v2-mean;
    float vs = d0*d0 + d1*d1 + d2*d2;
    #pragma unroll
    for (int o = 16; o > 0; o >>= 1) vs += __shfl_xor_sync(0xffffffffu, vs, o);
    float inv = rsqrtf(vs * (1.0f/96.0f) + 1e-6f);
    float y0 = d0*inv*g[lane]    + bb[lane];
    float y1 = d1*inv*g[lane+32] + bb[lane+32];
    float y2 = d2*inv*g[lane+64] + bb[lane+64];
    __nv_bfloat16* ph = hi + (size_t)row * 96;
    __nv_bfloat16* pl = lo + (size_t)row * 96;
    __nv_bfloat16 h, l;
    split_bf16(y0, h, l); ph[lane]    = h; pl[lane]    = l;
    split_bf16(y1, h, l); ph[lane+32] = h; pl[lane+32] = l;
    split_bf16(y2, h, l); ph[lane+64] = h; pl[lane+64] = l;
}

__global__ __launch_bounds__(256) void ln192b_kernel(
    const float* __restrict__ x, const float* __restrict__ g,
    const float* __restrict__ bb,
    __nv_bfloat16* __restrict__ hi, __nv_bfloat16* __restrict__ lo)
{
    int row  = blockIdx.x * 8 + (threadIdx.x >> 5);
    int lane = threadIdx.x & 31;
    const float* p = x + (size_t)row * 192;
    float v[6];
    float s = 0.f;
    #pragma unroll
    for (int i = 0; i < 6; i++) { v[i] = p[lane + 32*i]; s += v[i]; }
    #pragma unroll
    for (int o = 16; o > 0; o >>= 1) s += __shfl_xor_sync(0xffffffffu, s, o);
    float mean = s * (1.0f/192.0f);
    float vs = 0.f;
    #pragma unroll
    for (int i = 0; i < 6; i++) { v[i] -= mean; vs += v[i]*v[i]; }
    #pragma unroll
    for (int o = 16; o > 0; o >>= 1) vs += __shfl_xor_sync(0xffffffffu, vs, o);
    float inv = rsqrtf(vs * (1.0f/192.0f) + 1e-6f);
    __nv_bfloat16* ph = hi + (size_t)row * 192;
    __nv_bfloat16* pl = lo + (size_t)row * 192;
    #pragma unroll
    for (int i = 0; i < 6; i++) {
        float y = v[i]*inv*g[lane + 32*i] + bb[lane + 32*i];
        __nv_bfloat16 h, l;
        split_bf16(y, h, l);
        ph[lane + 32*i] = h; pl[lane + 32*i] = l;
    }
}

// ---------------- weight convert: W[K,N] fp32 -> [N][K] bf16 hi/lo ---------
__global__ __launch_bounds__(256) void conv_w_kernel(
    const float* __restrict__ W, __nv_bfloat16* __restrict__ hi,
    __nv_bfloat16* __restrict__ lo, int K, int N)
{
    int i = blockIdx.x * 256 + threadIdx.x;
    if (i >= N * K) return;
    int n = i / K, k = i % K;
    float v = W[(size_t)k * N + n];
    __nv_bfloat16 h, l;
    split_bf16(v, h, l);
    hi[i] = h; lo[i] = l;
}

// ---------------- 2x2 maxpool ----------------------------------------------
__global__ __launch_bounds__(256) void pool_kernel(
    const float* __restrict__ p, float* __restrict__ y)
{
    int i = blockIdx.x * 256 + threadIdx.x;
    int c   = i % 192;
    int pix = i / 192;
    int wp = pix & 127, hp = (pix >> 7) & 127, b = pix >> 14;
    size_t base = (((size_t)b*256 + hp*2)*256 + wp*2)*192 + c;
    const size_t rs = 256*192;
    y[i] = fmaxf(fmaxf(p[base], p[base+192]),
                 fmaxf(p[base+rs], p[base+rs+192]));
}

// ---------------- windowed attention (from passing R1) ---------------------
#define SM_QP   0
#define SM_KH   (16*192)
#define SM_VH   (SM_KH + 64*65)
#define SM_OW   (SM_VH + 64*64)
#define SM_SC   (SM_OW + 16*192)
#define SM_TOT  (SM_SC + 16*64)

__global__ __launch_bounds__(256) void attn_kernel(
    const float* __restrict__ qkv, const float* __restrict__ pw,
    const float* __restrict__ pb, float* __restrict__ y)
{
    extern __shared__ float sm[];
    float* qp = sm + SM_QP;
    float* kh = sm + SM_KH;
    float* vh = sm + SM_VH;
    float* ow = sm + SM_OW;
    float* sc = sm + SM_SC;

    int blk = blockIdx.x;
    int b = blk >> 10, wi = (blk >> 5) & 31, wj = blk & 31;
    int tid = threadIdx.x;

    for (int i = tid; i < 16*192; i += 256) {
        int t2 = i / 192, ch = i % 192;
        int r2 = t2 >> 2, c2 = t2 & 3;
        float m = -1e30f;
        #pragma unroll
        for (int dr = 0; dr < 2; dr++)
            #pragma unroll
            for (int dc = 0; dc < 2; dc++) {
                int r = r2*2 + dr, c = c2*2 + dc;
                int row = ((b*256 + wi*8 + r) << 8) + wj*8 + c;
                m = fmaxf(m, qkv[(size_t)row*576 + ch]);
            }
        qp[i] = m;
    }

    for (int h = 0; h < 3; h++) {
        __syncthreads();
        for (int i = tid; i < 64*64; i += 256) {
            int d = i & 63, s = i >> 6;
            int row = ((b*256 + wi*8 + (s >> 3)) << 8) + wj*8 + (s & 7);
            kh[d*65 + s] = qkv[(size_t)row*576 + 192 + h*64 + d];
        }
        for (int i = tid; i < 64*64; i += 256) {
            int d = i & 63, s = i >> 6;
            int row = ((b*256 + wi*8 + (s >> 3)) << 8) + wj*8 + (s & 7);
            vh[s*64 + d] = qkv[(size_t)row*576 + 384 + h*64 + d];
        }
        __syncthreads();
        for (int i = tid; i < 16*64; i += 256) {
            int t2 = i >> 6, s = i & 63;
            float acc = 0.f;
            #pragma unroll
            for (int d = 0; d < 64; d++)
                acc = fmaf(qp[t2*192 + h*64 + d], kh[d*65 + s], acc);
            sc[i] = acc * 0.125f;
        }
        __syncthreads();
        {
            int warp = tid >> 5, lane = tid & 31;
            for (int t2 = warp; t2 < 16; t2 += 8) {
                float v0 = sc[t2*64 + lane], v1 = sc[t2*64 + 32 + lane];
                float mx = fmaxf(v0, v1);
                #pragma unroll
                for (int o = 16; o > 0; o >>= 1)
                    mx = fmaxf(mx, __shfl_xor_sync(0xffffffffu, mx, o));
                float e0 = expf(v0 - mx), e1 = expf(v1 - mx);
                float ss = e0 + e1;
                #pragma unroll
                for (int o = 16; o > 0; o >>= 1)
                    ss += __shfl_xor_sync(0xffffffffu, ss, o);
                float inv = 1.f / ss;
                sc[t2*64 + lane]      = e0 * inv;
                sc[t2*64 + 32 + lane] = e1 * inv;
            }
        }
        __syncthreads();
        for (int i = tid; i < 16*64; i += 256) {
            int t2 = i >> 6, d = i & 63;
            float acc = 0.f;
            #pragma unroll
            for (int s = 0; s < 64; s++)
                acc = fmaf(sc[t2*64 + s], vh[s*64 + d], acc);
            ow[t2*192 + h*64 + d] = acc;
        }
    }
    __syncthreads();
    for (int i = tid; i < 16*192; i += 256) {
        int t2 = i / 192, col = i % 192;
        float acc = pb[col];
        #pragma unroll 8
        for (int k = 0; k < 192; k++)
            acc = fmaf(ow[t2*192 + k], pw[k*192 + col], acc);
        int r2 = t2 >> 2, c2 = t2 & 3;
        size_t orow = ((size_t)(b*128 + wi*4 + r2))*128 + wj*4 + c2;
        y[orow*192 + col] += acc;
    }
}

// ---------------- launch ----------------------------------------------------
extern "C" void kernel_launch(void* const* d_in, const int* in_sizes, int n_in,
                              void* d_out, int out_size)
{
    const float* x       = (const float*)d_in[0];
    const float* n1g     = (const float*)d_in[1];
    const float* n1b     = (const float*)d_in[2];
    const float* proj_w  = (const float*)d_in[3];
    const float* proj_b  = (const float*)d_in[4];
    const float* qkv_w   = (const float*)d_in[5];
    const float* qkv_b   = (const float*)d_in[6];
    const float* apw     = (const float*)d_in[7];
    const float* apb     = (const float*)d_in[8];
    const float* n2g     = (const float*)d_in[9];
    const float* n2b     = (const float*)d_in[10];
    const float* w1      = (const float*)d_in[11];
    const float* b1      = (const float*)d_in[12];
    const float* w2      = (const float*)d_in[13];
    const float* b2      = (const float*)d_in[14];
    float* y = (float*)d_out;

    __nv_bfloat16 *xh, *xl, *ynh, *ynl, *hh, *hl;
    __nv_bfloat16 *wph, *wpl, *wqh, *wql, *w1h, *w1l, *w2h, *w2l;
    float *proj, *qkv;
    cudaGetSymbolAddress((void**)&xh,  g_xh);
    cudaGetSymbolAddress((void**)&xl,  g_xl);
    cudaGetSymbolAddress((void**)&proj, g_proj);
    cudaGetSymbolAddress((void**)&qkv, g_qkv);
    cudaGetSymbolAddress((void**)&ynh, g_ynh);
    cudaGetSymbolAddress((void**)&ynl, g_ynl);
    cudaGetSymbolAddress((void**)&hh,  g_hh);
    cudaGetSymbolAddress((void**)&hl,  g_hl);
    cudaGetSymbolAddress((void**)&wph, g_wph);
    cudaGetSymbolAddress((void**)&wpl, g_wpl);
    cudaGetSymbolAddress((void**)&wqh, g_wqh);
    cudaGetSymbolAddress((void**)&wql, g_wql);
    cudaGetSymbolAddress((void**)&w1h, g_w1h);
    cudaGetSymbolAddress((void**)&w1l, g_w1l);
    cudaGetSymbolAddress((void**)&w2h, g_w2h);
    cudaGetSymbolAddress((void**)&w2l, g_w2l);

    static bool attr_done = false;
    if (!attr_done) {
        cudaFuncSetAttribute(attn_kernel,
            cudaFuncAttributeMaxDynamicSharedMemorySize, SM_TOT * 4);
        cudaFuncSetAttribute(gemm_mma,
            cudaFuncAttributeMaxDynamicSharedMemorySize, GEMM_SMEM);
        attr_done = true;
    }

    // weight conversions (tiny)
    conv_w_kernel<<<(192*96+255)/256, 256>>>(proj_w, wph, wpl, 96, 192);
    conv_w_kernel<<<(576*96+255)/256, 256>>>(qkv_w, wqh, wql, 96, 576);
    conv_w_kernel<<<(768*192+255)/256, 256>>>(w1, w1h, w1l, 192, 768);
    conv_w_kernel<<<(192*768+255)/256, 256>>>(w2, w2h, w2l, 768, 192);

    // 1) LN1 -> bf16 hi/lo
    ln96b_kernel<<<NPIX/8, 256>>>(x, n1g, n1b, xh, xl);
    // 2) proj GEMM -> proj (fp32)
    gemm_mma<<<dim3(192/96, NPIX/128), 256, GEMM_SMEM>>>(
        xh, xl, wph, wpl, 96, 192, 0, proj_b, proj, nullptr, nullptr, nullptr);
    // 3) maxpool -> y (shortcut)
    pool_kernel<<<(NPOOL*192)/256, 256>>>(proj, y);
    // 4) qkv GEMM -> qkv (fp32)
    gemm_mma<<<dim3(576/96, NPIX/128), 256, GEMM_SMEM>>>(
        xh, xl, wqh, wql, 96, 576, 0, qkv_b, qkv, nullptr, nullptr, nullptr);
    // 5) windowed attention (+= into y)
    attn_kernel<<<NWIN, 256, SM_TOT * 4>>>(qkv, apw, apb, y);
    // 6) LN2 -> bf16 hi/lo
    ln192b_kernel<<<NPOOL/8, 256>>>(y, n2g, n2b, ynh, ynl);
    // 7) mlp1 GEMM + gelu -> h (bf16 hi/lo)
    gemm_mma<<<dim3(768/96, NPOOL/128), 256, GEMM_SMEM>>>(
        ynh, ynl, w1h, w1l, 192, 768, 1, b1, nullptr, hh, hl, nullptr);
    // 8) mlp2 GEMM + residual add -> y (d_out)
    gemm_mma<<<dim3(192/96, NPOOL/128), 256, GEMM_SMEM>>>(
        hh, hl, w2h, w2l, 768, 192, 2, b2, y, nullptr, nullptr, y);
}

// round 4
// speedup vs baseline: 1.9719x; 1.2700x over previous
#include <cuda_runtime.h>
#include <cuda_bf16.h>
#include <cstdint>
#include <math.h>

// ===========================================================================
// MultiScaleBlock (sm_103 PTX, HMMA mma.sync path).
// bf16 hi/lo x3-product GEMMs, BN=192 wide tiles, 3-stage cp.async pipeline.
// Windowed attention computes O tile; attn-proj is a separate HMMA GEMM.
// ===========================================================================

#define NPIX   (4*256*256)     // 262144
#define NPOOL  (4*128*128)     // 65536
#define NWIN   (4*32*32)       // 4096

// ---------------- scratch (device globals) ----------------------------------
__device__ __nv_bfloat16 g_xh [(size_t)NPIX  * 96];
__device__ __nv_bfloat16 g_xl [(size_t)NPIX  * 96];
__device__ float         g_proj[(size_t)NPIX * 192];
__device__ float         g_qkv[(size_t)NPIX  * 576];
__device__ __nv_bfloat16 g_oh [(size_t)NPOOL * 192];
__device__ __nv_bfloat16 g_ol [(size_t)NPOOL * 192];
__device__ __nv_bfloat16 g_ynh[(size_t)NPOOL * 192];
__device__ __nv_bfloat16 g_ynl[(size_t)NPOOL * 192];
__device__ __nv_bfloat16 g_hh [(size_t)NPOOL * 768];
__device__ __nv_bfloat16 g_hl [(size_t)NPOOL * 768];
// weights converted to [N][K] bf16 hi/lo (transposed)
__device__ __nv_bfloat16 g_wph[192*96],  g_wpl[192*96];
__device__ __nv_bfloat16 g_wqh[576*96],  g_wql[576*96];
__device__ __nv_bfloat16 g_wah[192*192], g_wal[192*192];
__device__ __nv_bfloat16 g_w1h[768*192], g_w1l[768*192];
__device__ __nv_bfloat16 g_w2h[192*768], g_w2l[192*768];

// ---------------- helpers ---------------------------------------------------
__device__ __forceinline__ uint32_t smem_u32(const void* p) {
    uint32_t a;
    asm("{ .reg .u64 t; cvta.to.shared.u64 t, %1; cvt.u32.u64 %0, t; }"
        : "=r"(a) : "l"(p));
    return a;
}
__device__ __forceinline__ void cp16(uint32_t s, const void* g) {
    asm volatile("cp.async.ca.shared.global [%0], [%1], 16;"
                 :: "r"(s), "l"(g) : "memory");
}
__device__ __forceinline__ void cp_commit() {
    asm volatile("cp.async.commit_group;" ::: "memory");
}
template<int N>
__device__ __forceinline__ void cp_wait() {
    asm volatile("cp.async.wait_group %0;" :: "n"(N) : "memory");
}
__device__ __forceinline__ void ldsm4(uint32_t* r, uint32_t a) {
    asm volatile("ldmatrix.sync.aligned.m8n8.x4.shared.b16 {%0,%1,%2,%3}, [%4];"
        : "=r"(r[0]), "=r"(r[1]), "=r"(r[2]), "=r"(r[3]) : "r"(a));
}
__device__ __forceinline__ void mma_bf16(float* d, const uint32_t* a,
                                         uint32_t b0, uint32_t b1) {
    asm volatile(
        "mma.sync.aligned.m16n8k16.row.col.f32.bf16.bf16.f32 "
        "{%0,%1,%2,%3}, {%4,%5,%6,%7}, {%8,%9}, {%0,%1,%2,%3};"
        : "+f"(d[0]), "+f"(d[1]), "+f"(d[2]), "+f"(d[3])
        : "r"(a[0]), "r"(a[1]), "r"(a[2]), "r"(a[3]), "r"(b0), "r"(b1));
}
__device__ __forceinline__ void split_bf16(float v, __nv_bfloat16& h, __nv_bfloat16& l) {
    h = __float2bfloat16(v);
    l = __float2bfloat16(v - __bfloat162float(h));
}
__device__ __forceinline__ float gelu_exact(float v) {
    return 0.5f * v * (1.0f + erff(v * 0.70710678118654752f));
}

// ---------------- HMMA GEMM, BM=128 BN=192 BK=32, 3-stage -------------------
// C = A[M,K] @ B[N,K]^T (bf16 hi/lo x3), epi: 0 fp32+bias, 1 gelu->bf16 pair,
// 2 +bias+addsrc fp32.
#define LDA     40                         // BK + 8 (half-words)
#define SA_HI   0
#define SA_LO   (128*LDA*2)                // 10240
#define SB_HI   (2*128*LDA*2)              // 20480
#define SB_LO   (SB_HI + 192*LDA*2)        // 35840
#define STAGE_B (SB_LO + 192*LDA*2)        // 51200
#define GEMM_SMEM (3*STAGE_B)              // 153600

__global__ __launch_bounds__(256, 1) void gemm_mma(
    const __nv_bfloat16* __restrict__ Ah, const __nv_bfloat16* __restrict__ Al,
    const __nv_bfloat16* __restrict__ Bh, const __nv_bfloat16* __restrict__ Bl,
    int K, int N, int epi,
    const float* __restrict__ bias,
    float* __restrict__ Cf,
    __nv_bfloat16* __restrict__ Ch, __nv_bfloat16* __restrict__ Cl,
    const float* __restrict__ addsrc)
{
    extern __shared__ char smem[];
    const uint32_t sb = smem_u32(smem);
    const int tid = threadIdx.x, lane = tid & 31, warp = tid >> 5;
    const int wm = (warp >> 1) * 32;           // 4 warps in M
    const int wn = (warp & 1) * 96;            // 2 warps in N
    const size_t bm = (size_t)blockIdx.y * 128;
    const size_t bn = (size_t)blockIdx.x * 192;
    const int C = K >> 5;

    const __nv_bfloat16* AhB = Ah + bm * K;
    const __nv_bfloat16* AlB = Al + bm * K;
    const __nv_bfloat16* BhB = Bh + bn * K;
    const __nv_bfloat16* BlB = Bl + bn * K;

    float acc[2][12][4];
    #pragma unroll
    for (int i = 0; i < 2; i++)
        #pragma unroll
        for (int j = 0; j < 12; j++)
            #pragma unroll
            for (int q = 0; q < 4; q++) acc[i][j][q] = 0.f;

    auto load_stage = [&](int s, int c) {
        const uint32_t st = sb + (uint32_t)s * STAGE_B;
        const size_t k0 = (size_t)c * 32;
        #pragma unroll
        for (int i = tid; i < 512; i += 256) {       // A: 128 rows x 4 chunks
            int r = i >> 2, q = i & 3;
            uint32_t d = st + (uint32_t)(r * LDA + q * 8) * 2;
            size_t go = (size_t)r * K + k0 + q * 8;
            cp16(d + SA_HI, AhB + go);
            cp16(d + SA_LO, AlB + go);
        }
        #pragma unroll
        for (int i = tid; i < 768; i += 256) {       // B: 192 rows x 4 chunks
            int r = i >> 2, q = i & 3;
            uint32_t d = st + (uint32_t)(r * LDA + q * 8) * 2;
            size_t go = (size_t)r * K + k0 + q * 8;
            cp16(d + SB_HI, BhB + go);
            cp16(d + SB_LO, BlB + go);
        }
        cp_commit();
    };

    auto compute_stage = [&](int s) {
        const uint32_t st = sb + (uint32_t)s * STAGE_B;
        #pragma unroll
        for (int k16 = 0; k16 < 2; k16++) {
            uint32_t ah[2][4], al[2][4];
            #pragma unroll
            for (int mi = 0; mi < 2; mi++) {
                int row = wm + mi * 16 + (lane & 15);
                int col = k16 * 16 + (lane >> 4) * 8;
                uint32_t ad = st + (uint32_t)(row * LDA + col) * 2;
                ldsm4(ah[mi], ad + SA_HI);
                ldsm4(al[mi], ad + SA_LO);
            }
            #pragma unroll
            for (int ng = 0; ng < 6; ng++) {
                uint32_t bh[4], bl[4];
                int nr = wn + ng * 16 + (lane & 7) + ((lane >> 4) & 1) * 8;
                int bc = k16 * 16 + ((lane >> 3) & 1) * 8;
                uint32_t bd = st + (uint32_t)(nr * LDA + bc) * 2;
                ldsm4(bh, bd + SB_HI);
                ldsm4(bl, bd + SB_LO);
                #pragma unroll
                for (int mi = 0; mi < 2; mi++) {
                    #pragma unroll
                    for (int sub = 0; sub < 2; sub++) {
                        float* d = acc[mi][ng * 2 + sub];
                        mma_bf16(d, ah[mi], bh[2*sub], bh[2*sub+1]);
                        mma_bf16(d, ah[mi], bl[2*sub], bl[2*sub+1]);
                        mma_bf16(d, al[mi], bh[2*sub], bh[2*sub+1]);
                    }
                }
            }
        }
    };

    // ---- 3-stage pipeline ----
    load_stage(0, 0);
    load_stage(1, 1);
    for (int c = 0; c < C; c++) {
        if (c + 1 < C) { cp_wait<1>(); } else { cp_wait<0>(); }
        __syncthreads();
        if (c + 2 < C) load_stage((c + 2) % 3, c + 2);
        compute_stage(c % 3);
        __syncthreads();
    }

    // ---- epilogue ----
    #pragma unroll
    for (int mi = 0; mi < 2; mi++) {
        #pragma unroll
        for (int nj = 0; nj < 12; nj++) {
            size_t row0 = bm + wm + mi * 16 + (lane >> 2);
            size_t col  = bn + wn + nj * 8 + 2 * (lane & 3);
            float b0 = bias[col], b1 = bias[col + 1];
            float v00 = acc[mi][nj][0] + b0, v01 = acc[mi][nj][1] + b1;
            float v10 = acc[mi][nj][2] + b0, v11 = acc[mi][nj][3] + b1;
            if (epi == 0) {
                *reinterpret_cast<float2*>(Cf + row0 * N + col)       = make_float2(v00, v01);
                *reinterpret_cast<float2*>(Cf + (row0 + 8) * N + col) = make_float2(v10, v11);
            } else if (epi == 1) {
                v00 = gelu_exact(v00); v01 = gelu_exact(v01);
                v10 = gelu_exact(v10); v11 = gelu_exact(v11);
                __nv_bfloat16 h, l;
                __nv_bfloat162 hp, lp;
                split_bf16(v00, h, l); hp.x = h; lp.x = l;
                split_bf16(v01, h, l); hp.y = h; lp.y = l;
                *reinterpret_cast<__nv_bfloat162*>(Ch + row0 * N + col) = hp;
                *reinterpret_cast<__nv_bfloat162*>(Cl + row0 * N + col) = lp;
                split_bf16(v10, h, l); hp.x = h; lp.x = l;
                split_bf16(v11, h, l); hp.y = h; lp.y = l;
                *reinterpret_cast<__nv_bfloat162*>(Ch + (row0 + 8) * N + col) = hp;
                *reinterpret_cast<__nv_bfloat162*>(Cl + (row0 + 8) * N + col) = lp;
            } else {
                const float2 a0 = *reinterpret_cast<const float2*>(addsrc + row0 * N + col);
                const float2 a1 = *reinterpret_cast<const float2*>(addsrc + (row0 + 8) * N + col);
                *reinterpret_cast<float2*>(Cf + row0 * N + col)       = make_float2(v00 + a0.x, v01 + a0.y);
                *reinterpret_cast<float2*>(Cf + (row0 + 8) * N + col) = make_float2(v10 + a1.x, v11 + a1.y);
            }
        }
    }
}

// ---------------- LayerNorm -> bf16 hi/lo ----------------------------------
__global__ __launch_bounds__(256) void ln96b_kernel(
    const float* __restrict__ x, const float* __restrict__ g,
    const float* __restrict__ bb,
    __nv_bfloat16* __restrict__ hi, __nv_bfloat16* __restrict__ lo)
{
    int row  = blockIdx.x * 8 + (threadIdx.x >> 5);
    int lane = threadIdx.x & 31;
    const float* p = x + (size_t)row * 96;
    float v0 = p[lane], v1 = p[lane+32], v2 = p[lane+64];
    float s = v0 + v1 + v2;
    #pragma unroll
    for (int o = 16; o > 0; o >>= 1) s += __shfl_xor_sync(0xffffffffu, s, o);
    float mean = s * (1.0f/96.0f);
    float d0 = v0-mean, d1 = v1-mean, d2 = v2-mean;
    float vs = d0*d0 + d1*d1 + d2*d2;
    #pragma unroll
    for (int o = 16; o > 0; o >>= 1) vs += __shfl_xor_sync(0xffffffffu, vs, o);
    float inv = rsqrtf(vs * (1.0f/96.0f) + 1e-6f);
    float y0 = d0*inv*g[lane]    + bb[lane];
    float y1 = d1*inv*g[lane+32] + bb[lane+32];
    float y2 = d2*inv*g[lane+64] + bb[lane+64];
    __nv_bfloat16* ph = hi + (size_t)row * 96;
    __nv_bfloat16* pl = lo + (size_t)row * 96;
    __nv_bfloat16 h, l;
    split_bf16(y0, h, l); ph[lane]    = h; pl[lane]    = l;
    split_bf16(y1, h, l); ph[lane+32] = h; pl[lane+32] = l;
    split_bf16(y2, h, l); ph[lane+64] = h; pl[lane+64] = l;
}

__global__ __launch_bounds__(256) void ln192b_kernel(
    const float* __restrict__ x, const float* __restrict__ g,
    const float* __restrict__ bb,
    __nv_bfloat16* __restrict__ hi, __nv_bfloat16* __restrict__ lo)
{
    int row  = blockIdx.x * 8 + (threadIdx.x >> 5);
    int lane = threadIdx.x & 31;
    const float* p = x + (size_t)row * 192;
    float v[6];
    float s = 0.f;
    #pragma unroll
    for (int i = 0; i < 6; i++) { v[i] = p[lane + 32*i]; s += v[i]; }
    #pragma unroll
    for (int o = 16; o > 0; o >>= 1) s += __shfl_xor_sync(0xffffffffu, s, o);
    float mean = s * (1.0f/192.0f);
    float vs = 0.f;
    #pragma unroll
    for (int i = 0; i < 6; i++) { v[i] -= mean; vs += v[i]*v[i]; }
    #pragma unroll
    for (int o = 16; o > 0; o >>= 1) vs += __shfl_xor_sync(0xffffffffu, vs, o);
    float inv = rsqrtf(vs * (1.0f/192.0f) + 1e-6f);
    __nv_bfloat16* ph = hi + (size_t)row * 192;
    __nv_bfloat16* pl = lo + (size_t)row * 192;
    #pragma unroll
    for (int i = 0; i < 6; i++) {
        float y = v[i]*inv*g[lane + 32*i] + bb[lane + 32*i];
        __nv_bfloat16 h, l;
        split_bf16(y, h, l);
        ph[lane + 32*i] = h; pl[lane + 32*i] = l;
    }
}

// ---------------- weight convert: W[K,N] fp32 -> [N][K] bf16 hi/lo ---------
__global__ __launch_bounds__(256) void conv_w_kernel(
    const float* __restrict__ W, __nv_bfloat16* __restrict__ hi,
    __nv_bfloat16* __restrict__ lo, int K, int N)
{
    int i = blockIdx.x * 256 + threadIdx.x;
    if (i >= N * K) return;
    int n = i / K, k = i % K;
    float v = W[(size_t)k * N + n];
    __nv_bfloat16 h, l;
    split_bf16(v, h, l);
    hi[i] = h; lo[i] = l;
}

// ---------------- 2x2 maxpool ----------------------------------------------
__global__ __launch_bounds__(256) void pool_kernel(
    const float* __restrict__ p, float* __restrict__ y)
{
    int i = blockIdx.x * 256 + threadIdx.x;
    int c   = i % 192;
    int pix = i / 192;
    int wp = pix & 127, hp = (pix >> 7) & 127, b = pix >> 14;
    size_t base = (((size_t)b*256 + hp*2)*256 + wp*2)*192 + c;
    const size_t rs = 256*192;
    y[i] = fmaxf(fmaxf(p[base], p[base+192]),
                 fmaxf(p[base+rs], p[base+rs+192]));
}

// ---------------- windowed attention -> O tile (bf16 hi/lo) -----------------
// Per window: q-pool (16 tokens x 192), 3 heads of softmax attention over 64
// keys; O written in pooled-pixel row order for the following attn-proj GEMM.
#define AQP   0                          // 16*192 = 3072
#define AKH   3072                       // 64*68 (kh[s][d], s-major)
#define AVH   (AKH + 64*68)              // 64*68 (vh[d][s], d-major)
#define ASC   (AVH + 64*68)              // 16*64
#define ATOT  (ASC + 16*64)              // 12800 floats = 51200 B

__global__ __launch_bounds__(256) void attn_kernel(
    const float* __restrict__ qkv,
    __nv_bfloat16* __restrict__ Oh, __nv_bfloat16* __restrict__ Ol)
{
    extern __shared__ float sm[];
    float* qp = sm + AQP;
    float* kh = sm + AKH;     // [s][d] stride 68
    float* vh = sm + AVH;     // [d][s] stride 68
    float* sc = sm + ASC;     // [t2][s]

    int blk = blockIdx.x;
    int b = blk >> 10, wi = (blk >> 5) & 31, wj = blk & 31;
    int tid = threadIdx.x;

    // pooled q
    for (int i = tid; i < 16*192; i += 256) {
        int t2 = i / 192, ch = i % 192;
        int r2 = t2 >> 2, c2 = t2 & 3;
        float m = -1e30f;
        #pragma unroll
        for (int dr = 0; dr < 2; dr++)
            #pragma unroll
            for (int dc = 0; dc < 2; dc++) {
                int row = ((b*256 + wi*8 + r2*2 + dr) << 8) + wj*8 + c2*2 + dc;
                m = fmaxf(m, qkv[(size_t)row*576 + ch]);
            }
        qp[i] = m;
    }

    for (int h = 0; h < 3; h++) {
        __syncthreads();
        for (int i = tid; i < 64*64; i += 256) {
            int d = i & 63, s = i >> 6;
            int row = ((b*256 + wi*8 + (s >> 3)) << 8) + wj*8 + (s & 7);
            kh[s*68 + d] = qkv[(size_t)row*576 + 192 + h*64 + d];
            vh[d*68 + s] = qkv[(size_t)row*576 + 384 + h*64 + d];
        }
        __syncthreads();
        // scores: thread=(t2,s), float4 over d
        for (int i = tid; i < 16*64; i += 256) {
            int t2 = i >> 6, s = i & 63;
            const float4* qv = reinterpret_cast<const float4*>(&qp[t2*192 + h*64]);
            const float4* kv = reinterpret_cast<const float4*>(&kh[s*68]);
            float acc = 0.f;
            #pragma unroll
            for (int d4 = 0; d4 < 16; d4++) {
                float4 a = qv[d4], bq = kv[d4];
                acc = fmaf(a.x, bq.x, acc);
                acc = fmaf(a.y, bq.y, acc);
                acc = fmaf(a.z, bq.z, acc);
                acc = fmaf(a.w, bq.w, acc);
            }
            sc[i] = acc * 0.125f;
        }
        __syncthreads();
        // softmax per t2 row (warp per row)
        {
            int warp = tid >> 5, lane = tid & 31;
            for (int t2 = warp; t2 < 16; t2 += 8) {
                float v0 = sc[t2*64 + lane], v1 = sc[t2*64 + 32 + lane];
                float mx = fmaxf(v0, v1);
                #pragma unroll
                for (int o = 16; o > 0; o >>= 1)
                    mx = fmaxf(mx, __shfl_xor_sync(0xffffffffu, mx, o));
                float e0 = expf(v0 - mx), e1 = expf(v1 - mx);
                float ss = e0 + e1;
                #pragma unroll
                for (int o = 16; o > 0; o >>= 1)
                    ss += __shfl_xor_sync(0xffffffffu, ss, o);
                float inv = 1.f / ss;
                sc[t2*64 + lane]      = e0 * inv;
                sc[t2*64 + 32 + lane] = e1 * inv;
            }
        }
        __syncthreads();
        // out: thread=(t2,d), float4 over s, write O (bf16 hi/lo) to global
        for (int i = tid; i < 16*64; i += 256) {
            int t2 = i >> 6, d = i & 63;
            const float4* pv = reinterpret_cast<const float4*>(&sc[t2*64]);
            const float4* vv = reinterpret_cast<const float4*>(&vh[d*68]);
            float acc = 0.f;
            #pragma unroll
            for (int s4 = 0; s4 < 16; s4++) {
                float4 a = pv[s4], bv = vv[s4];
                acc = fmaf(a.x, bv.x, acc);
                acc = fmaf(a.y, bv.y, acc);
                acc = fmaf(a.z, bv.z, acc);
                acc = fmaf(a.w, bv.w, acc);
            }
            int r2 = t2 >> 2, c2 = t2 & 3;
            size_t orow = ((size_t)(b*128 + wi*4 + r2))*128 + wj*4 + c2;
            __nv_bfloat16 hh, ll;
            split_bf16(acc, hh, ll);
            Oh[orow*192 + h*64 + d] = hh;
            Ol[orow*192 + h*64 + d] = ll;
        }
    }
}

// ---------------- launch ----------------------------------------------------
extern "C" void kernel_launch(void* const* d_in, const int* in_sizes, int n_in,
                              void* d_out, int out_size)
{
    const float* x       = (const float*)d_in[0];
    const float* n1g     = (const float*)d_in[1];
    const float* n1b     = (const float*)d_in[2];
    const float* proj_w  = (const float*)d_in[3];
    const float* proj_b  = (const float*)d_in[4];
    const float* qkv_w   = (const float*)d_in[5];
    const float* qkv_b   = (const float*)d_in[6];
    const float* apw     = (const float*)d_in[7];
    const float* apb     = (const float*)d_in[8];
    const float* n2g     = (const float*)d_in[9];
    const float* n2b     = (const float*)d_in[10];
    const float* w1      = (const float*)d_in[11];
    const float* b1      = (const float*)d_in[12];
    const float* w2      = (const float*)d_in[13];
    const float* b2      = (const float*)d_in[14];
    float* y = (float*)d_out;

    __nv_bfloat16 *xh, *xl, *oh, *ol, *ynh, *ynl, *hh, *hl;
    __nv_bfloat16 *wph, *wpl, *wqh, *wql, *wah, *wal, *w1h, *w1l, *w2h, *w2l;
    float *proj, *qkv;
    cudaGetSymbolAddress((void**)&xh,  g_xh);
    cudaGetSymbolAddress((void**)&xl,  g_xl);
    cudaGetSymbolAddress((void**)&proj, g_proj);
    cudaGetSymbolAddress((void**)&qkv, g_qkv);
    cudaGetSymbolAddress((void**)&oh,  g_oh);
    cudaGetSymbolAddress((void**)&ol,  g_ol);
    cudaGetSymbolAddress((void**)&ynh, g_ynh);
    cudaGetSymbolAddress((void**)&ynl, g_ynl);
    cudaGetSymbolAddress((void**)&hh,  g_hh);
    cudaGetSymbolAddress((void**)&hl,  g_hl);
    cudaGetSymbolAddress((void**)&wph, g_wph);
    cudaGetSymbolAddress((void**)&wpl, g_wpl);
    cudaGetSymbolAddress((void**)&wqh, g_wqh);
    cudaGetSymbolAddress((void**)&wql, g_wql);
    cudaGetSymbolAddress((void**)&wah, g_wah);
    cudaGetSymbolAddress((void**)&wal, g_wal);
    cudaGetSymbolAddress((void**)&w1h, g_w1h);
    cudaGetSymbolAddress((void**)&w1l, g_w1l);
    cudaGetSymbolAddress((void**)&w2h, g_w2h);
    cudaGetSymbolAddress((void**)&w2l, g_w2l);

    static bool attr_done = false;
    if (!attr_done) {
        cudaFuncSetAttribute(attn_kernel,
            cudaFuncAttributeMaxDynamicSharedMemorySize, ATOT * 4);
        cudaFuncSetAttribute(gemm_mma,
            cudaFuncAttributeMaxDynamicSharedMemorySize, GEMM_SMEM);
        attr_done = true;
    }

    // weight conversions (tiny)
    conv_w_kernel<<<(192*96+255)/256, 256>>>(proj_w, wph, wpl, 96, 192);
    conv_w_kernel<<<(576*96+255)/256, 256>>>(qkv_w, wqh, wql, 96, 576);
    conv_w_kernel<<<(192*192+255)/256, 256>>>(apw, wah, wal, 192, 192);
    conv_w_kernel<<<(768*192+255)/256, 256>>>(w1, w1h, w1l, 192, 768);
    conv_w_kernel<<<(192*768+255)/256, 256>>>(w2, w2h, w2l, 768, 192);

    // 1) LN1 -> bf16 hi/lo
    ln96b_kernel<<<NPIX/8, 256>>>(x, n1g, n1b, xh, xl);
    // 2) proj GEMM -> proj (fp32)
    gemm_mma<<<dim3(1, NPIX/128), 256, GEMM_SMEM>>>(
        xh, xl, wph, wpl, 96, 192, 0, proj_b, proj, nullptr, nullptr, nullptr);
    // 3) maxpool -> y (shortcut)
    pool_kernel<<<(NPOOL*192)/256, 256>>>(proj, y);
    // 4) qkv GEMM -> qkv (fp32)
    gemm_mma<<<dim3(3, NPIX/128), 256, GEMM_SMEM>>>(
        xh, xl, wqh, wql, 96, 576, 0, qkv_b, qkv, nullptr, nullptr, nullptr);
    // 5) windowed attention -> O (bf16 hi/lo)
    attn_kernel<<<NWIN, 256, ATOT * 4>>>(qkv, oh, ol);
    // 6) attn-proj GEMM: y += O @ apw + apb
    gemm_mma<<<dim3(1, NPOOL/128), 256, GEMM_SMEM>>>(
        oh, ol, wah, wal, 192, 192, 2, apb, y, nullptr, nullptr, y);
    // 7) LN2 -> bf16 hi/lo
    ln192b_kernel<<<NPOOL/8, 256>>>(y, n2g, n2b, ynh, ynl);
    // 8) mlp1 GEMM + gelu -> h (bf16 hi/lo)
    gemm_mma<<<dim3(4, NPOOL/128), 256, GEMM_SMEM>>>(
        ynh, ynl, w1h, w1l, 192, 768, 1, b1, nullptr, hh, hl, nullptr);
    // 9) mlp2 GEMM + residual add -> y (d_out)
    gemm_mma<<<dim3(1, NPOOL/128), 256, GEMM_SMEM>>>(
        hh, hl, w2h, w2l, 768, 192, 2, b2, y, nullptr, nullptr, y);
}

// round 5
// speedup vs baseline: 2.0895x; 1.0596x over previous
#include <cuda_runtime.h>
#include <cuda_bf16.h>
#include <cstdint>
#include <math.h>

// ===========================================================================
// MultiScaleBlock (sm_103 PTX, HMMA mma.sync path).
// bf16 hi/lo x3-product GEMMs; fused proj+qkv GEMM (N=768) with bf16 qkv;
// bf16 attention loads; attn-proj / mlp on the same GEMM kernel.
// ===========================================================================

#define NPIX   (4*256*256)     // 262144
#define NPOOL  (4*128*128)     // 65536
#define NWIN   (4*32*32)       // 4096

// ---------------- scratch (device globals) ----------------------------------
__device__ __nv_bfloat16 g_xh [(size_t)NPIX  * 96];
__device__ __nv_bfloat16 g_xl [(size_t)NPIX  * 96];
__device__ float         g_proj[(size_t)NPIX * 192];
__device__ __nv_bfloat16 g_qkvb[(size_t)NPIX * 576];     // bf16 qkv
__device__ __nv_bfloat16 g_oh [(size_t)NPOOL * 192];
__device__ __nv_bfloat16 g_ol [(size_t)NPOOL * 192];
__device__ __nv_bfloat16 g_ynh[(size_t)NPOOL * 192];
__device__ __nv_bfloat16 g_ynl[(size_t)NPOOL * 192];
__device__ __nv_bfloat16 g_hh [(size_t)NPOOL * 768];
__device__ __nv_bfloat16 g_hl [(size_t)NPOOL * 768];
// weights [N][K] bf16 hi/lo (transposed); proj+qkv fused into 768 rows
__device__ __nv_bfloat16 g_wfh[768*96],  g_wfl[768*96];
__device__ __nv_bfloat16 g_wah[192*192], g_wal[192*192];
__device__ __nv_bfloat16 g_w1h[768*192], g_w1l[768*192];
__device__ __nv_bfloat16 g_w2h[192*768], g_w2l[192*768];
__device__ float         g_b768[768];

// ---------------- helpers ---------------------------------------------------
__device__ __forceinline__ uint32_t smem_u32(const void* p) {
    uint32_t a;
    asm("{ .reg .u64 t; cvta.to.shared.u64 t, %1; cvt.u32.u64 %0, t; }"
        : "=r"(a) : "l"(p));
    return a;
}
__device__ __forceinline__ void cp16(uint32_t s, const void* g) {
    asm volatile("cp.async.ca.shared.global [%0], [%1], 16;"
                 :: "r"(s), "l"(g) : "memory");
}
__device__ __forceinline__ void cp_commit() {
    asm volatile("cp.async.commit_group;" ::: "memory");
}
template<int N>
__device__ __forceinline__ void cp_wait() {
    asm volatile("cp.async.wait_group %0;" :: "n"(N) : "memory");
}
__device__ __forceinline__ void ldsm4(uint32_t* r, uint32_t a) {
    asm volatile("ldmatrix.sync.aligned.m8n8.x4.shared.b16 {%0,%1,%2,%3}, [%4];"
        : "=r"(r[0]), "=r"(r[1]), "=r"(r[2]), "=r"(r[3]) : "r"(a));
}
__device__ __forceinline__ void mma_bf16(float* d, const uint32_t* a,
                                         uint32_t b0, uint32_t b1) {
    asm volatile(
        "mma.sync.aligned.m16n8k16.row.col.f32.bf16.bf16.f32 "
        "{%0,%1,%2,%3}, {%4,%5,%6,%7}, {%8,%9}, {%0,%1,%2,%3};"
        : "+f"(d[0]), "+f"(d[1]), "+f"(d[2]), "+f"(d[3])
        : "r"(a[0]), "r"(a[1]), "r"(a[2]), "r"(a[3]), "r"(b0), "r"(b1));
}
__device__ __forceinline__ void split_bf16(float v, __nv_bfloat16& h, __nv_bfloat16& l) {
    h = __float2bfloat16(v);
    l = __float2bfloat16(v - __bfloat162float(h));
}
__device__ __forceinline__ float gelu_exact(float v) {
    return 0.5f * v * (1.0f + erff(v * 0.70710678118654752f));
}

// ---------------- HMMA GEMM, BM=128 BN=192 BK=32, 3-stage -------------------
// C = A[M,K] @ B[N,K]^T (bf16 hi/lo x3).
// epi: 0 fp32+bias; 1 gelu->bf16 hi/lo; 2 +bias+addsrc fp32;
//      3 fused proj/qkv (x-tile 0 -> Cf fp32 ld192, tiles 1..3 -> Ch bf16 ld576)
#define LDA     40                         // BK + 8 (half-words)
#define SA_HI   0
#define SA_LO   (128*LDA*2)                // 10240
#define SB_HI   (2*128*LDA*2)              // 20480
#define SB_LO   (SB_HI + 192*LDA*2)        // 35840
#define STAGE_B (SB_LO + 192*LDA*2)        // 51200
#define GEMM_SMEM (3*STAGE_B)              // 153600

__global__ __launch_bounds__(256, 1) void gemm_mma(
    const __nv_bfloat16* __restrict__ Ah, const __nv_bfloat16* __restrict__ Al,
    const __nv_bfloat16* __restrict__ Bh, const __nv_bfloat16* __restrict__ Bl,
    int K, int N, int epi,
    const float* __restrict__ bias,
    float* __restrict__ Cf,
    __nv_bfloat16* __restrict__ Ch, __nv_bfloat16* __restrict__ Cl,
    const float* __restrict__ addsrc)
{
    extern __shared__ char smem[];
    const uint32_t sb = smem_u32(smem);
    const int tid = threadIdx.x, lane = tid & 31, warp = tid >> 5;
    const int wm = (warp >> 1) * 32;           // 4 warps in M
    const int wn = (warp & 1) * 96;            // 2 warps in N
    const size_t bm = (size_t)blockIdx.y * 128;
    const size_t bn = (size_t)blockIdx.x * 192;
    const int C = K >> 5;

    const __nv_bfloat16* AhB = Ah + bm * K;
    const __nv_bfloat16* AlB = Al + bm * K;
    const __nv_bfloat16* BhB = Bh + bn * K;
    const __nv_bfloat16* BlB = Bl + bn * K;

    float acc[2][12][4];
    #pragma unroll
    for (int i = 0; i < 2; i++)
        #pragma unroll
        for (int j = 0; j < 12; j++)
            #pragma unroll
            for (int q = 0; q < 4; q++) acc[i][j][q] = 0.f;

    auto load_stage = [&](int s, int c) {
        const uint32_t st = sb + (uint32_t)s * STAGE_B;
        const size_t k0 = (size_t)c * 32;
        #pragma unroll
        for (int i = tid; i < 512; i += 256) {       // A: 128 rows x 4 chunks
            int r = i >> 2, q = i & 3;
            uint32_t d = st + (uint32_t)(r * LDA + q * 8) * 2;
            size_t go = (size_t)r * K + k0 + q * 8;
            cp16(d + SA_HI, AhB + go);
            cp16(d + SA_LO, AlB + go);
        }
        #pragma unroll
        for (int i = tid; i < 768; i += 256) {       // B: 192 rows x 4 chunks
            int r = i >> 2, q = i & 3;
            uint32_t d = st + (uint32_t)(r * LDA + q * 8) * 2;
            size_t go = (size_t)r * K + k0 + q * 8;
            cp16(d + SB_HI, BhB + go);
            cp16(d + SB_LO, BlB + go);
        }
        cp_commit();
    };

    auto compute_stage = [&](int s) {
        const uint32_t st = sb + (uint32_t)s * STAGE_B;
        #pragma unroll
        for (int k16 = 0; k16 < 2; k16++) {
            uint32_t ah[2][4], al[2][4];
            #pragma unroll
            for (int mi = 0; mi < 2; mi++) {
                int row = wm + mi * 16 + (lane & 15);
                int col = k16 * 16 + (lane >> 4) * 8;
                uint32_t ad = st + (uint32_t)(row * LDA + col) * 2;
                ldsm4(ah[mi], ad + SA_HI);
                ldsm4(al[mi], ad + SA_LO);
            }
            #pragma unroll
            for (int ng = 0; ng < 6; ng++) {
                uint32_t bh[4], bl[4];
                int nr = wn + ng * 16 + (lane & 7) + ((lane >> 4) & 1) * 8;
                int bc = k16 * 16 + ((lane >> 3) & 1) * 8;
                uint32_t bd = st + (uint32_t)(nr * LDA + bc) * 2;
                ldsm4(bh, bd + SB_HI);
                ldsm4(bl, bd + SB_LO);
                #pragma unroll
                for (int mi = 0; mi < 2; mi++) {
                    #pragma unroll
                    for (int sub = 0; sub < 2; sub++) {
                        float* d = acc[mi][ng * 2 + sub];
                        mma_bf16(d, ah[mi], bh[2*sub], bh[2*sub+1]);
                        mma_bf16(d, ah[mi], bl[2*sub], bl[2*sub+1]);
                        mma_bf16(d, al[mi], bh[2*sub], bh[2*sub+1]);
                    }
                }
            }
        }
    };

    // ---- 3-stage pipeline ----
    load_stage(0, 0);
    load_stage(1, 1);
    for (int c = 0; c < C; c++) {
        if (c + 1 < C) { cp_wait<1>(); } else { cp_wait<0>(); }
        __syncthreads();
        if (c + 2 < C) load_stage((c + 2) % 3, c + 2);
        compute_stage(c % 3);
        __syncthreads();
    }

    // ---- epilogue ----
    #pragma unroll
    for (int mi = 0; mi < 2; mi++) {
        #pragma unroll
        for (int nj = 0; nj < 12; nj++) {
            size_t row0 = bm + wm + mi * 16 + (lane >> 2);
            size_t col  = bn + wn + nj * 8 + 2 * (lane & 3);
            float b0 = bias[col], b1 = bias[col + 1];
            float v00 = acc[mi][nj][0] + b0, v01 = acc[mi][nj][1] + b1;
            float v10 = acc[mi][nj][2] + b0, v11 = acc[mi][nj][3] + b1;
            if (epi == 0) {
                *reinterpret_cast<float2*>(Cf + row0 * N + col)       = make_float2(v00, v01);
                *reinterpret_cast<float2*>(Cf + (row0 + 8) * N + col) = make_float2(v10, v11);
            } else if (epi == 1) {
                v00 = gelu_exact(v00); v01 = gelu_exact(v01);
                v10 = gelu_exact(v10); v11 = gelu_exact(v11);
                __nv_bfloat16 h, l;
                __nv_bfloat162 hp, lp;
                split_bf16(v00, h, l); hp.x = h; lp.x = l;
                split_bf16(v01, h, l); hp.y = h; lp.y = l;
                *reinterpret_cast<__nv_bfloat162*>(Ch + row0 * N + col) = hp;
                *reinterpret_cast<__nv_bfloat162*>(Cl + row0 * N + col) = lp;
                split_bf16(v10, h, l); hp.x = h; lp.x = l;
                split_bf16(v11, h, l); hp.y = h; lp.y = l;
                *reinterpret_cast<__nv_bfloat162*>(Ch + (row0 + 8) * N + col) = hp;
                *reinterpret_cast<__nv_bfloat162*>(Cl + (row0 + 8) * N + col) = lp;
            } else if (epi == 2) {
                const float2 a0 = *reinterpret_cast<const float2*>(addsrc + row0 * N + col);
                const float2 a1 = *reinterpret_cast<const float2*>(addsrc + (row0 + 8) * N + col);
                *reinterpret_cast<float2*>(Cf + row0 * N + col)       = make_float2(v00 + a0.x, v01 + a0.y);
                *reinterpret_cast<float2*>(Cf + (row0 + 8) * N + col) = make_float2(v10 + a1.x, v11 + a1.y);
            } else {  // epi == 3: fused proj (tile 0, fp32) / qkv (tiles 1-3, bf16)
                if (bn == 0) {
                    *reinterpret_cast<float2*>(Cf + row0 * 192 + col)       = make_float2(v00, v01);
                    *reinterpret_cast<float2*>(Cf + (row0 + 8) * 192 + col) = make_float2(v10, v11);
                } else {
                    size_t qc = col - 192;
                    __nv_bfloat162 p0, p1;
                    p0.x = __float2bfloat16(v00); p0.y = __float2bfloat16(v01);
                    p1.x = __float2bfloat16(v10); p1.y = __float2bfloat16(v11);
                    *reinterpret_cast<__nv_bfloat162*>(Ch + row0 * 576 + qc)       = p0;
                    *reinterpret_cast<__nv_bfloat162*>(Ch + (row0 + 8) * 576 + qc) = p1;
                }
            }
        }
    }
}

// ---------------- LayerNorm -> bf16 hi/lo ----------------------------------
__global__ __launch_bounds__(256) void ln96b_kernel(
    const float* __restrict__ x, const float* __restrict__ g,
    const float* __restrict__ bb,
    __nv_bfloat16* __restrict__ hi, __nv_bfloat16* __restrict__ lo)
{
    int row  = blockIdx.x * 8 + (threadIdx.x >> 5);
    int lane = threadIdx.x & 31;
    const float* p = x + (size_t)row * 96;
    float v0 = p[lane], v1 = p[lane+32], v2 = p[lane+64];
    float s = v0 + v1 + v2;
    #pragma unroll
    for (int o = 16; o > 0; o >>= 1) s += __shfl_xor_sync(0xffffffffu, s, o);
    float mean = s * (1.0f/96.0f);
    float d0 = v0-mean, d1 = v1-mean, d2 = v2-mean;
    float vs = d0*d0 + d1*d1 + d2*d2;
    #pragma unroll
    for (int o = 16; o > 0; o >>= 1) vs += __shfl_xor_sync(0xffffffffu, vs, o);
    float inv = rsqrtf(vs * (1.0f/96.0f) + 1e-6f);
    float y0 = d0*inv*g[lane]    + bb[lane];
    float y1 = d1*inv*g[lane+32] + bb[lane+32];
    float y2 = d2*inv*g[lane+64] + bb[lane+64];
    __nv_bfloat16* ph = hi + (size_t)row * 96;
    __nv_bfloat16* pl = lo + (size_t)row * 96;
    __nv_bfloat16 h, l;
    split_bf16(y0, h, l); ph[lane]    = h; pl[lane]    = l;
    split_bf16(y1, h, l); ph[lane+32] = h; pl[lane+32] = l;
    split_bf16(y2, h, l); ph[lane+64] = h; pl[lane+64] = l;
}

__global__ __launch_bounds__(256) void ln192b_kernel(
    const float* __restrict__ x, const float* __restrict__ g,
    const float* __restrict__ bb,
    __nv_bfloat16* __restrict__ hi, __nv_bfloat16* __restrict__ lo)
{
    int row  = blockIdx.x * 8 + (threadIdx.x >> 5);
    int lane = threadIdx.x & 31;
    const float* p = x + (size_t)row * 192;
    float v[6];
    float s = 0.f;
    #pragma unroll
    for (int i = 0; i < 6; i++) { v[i] = p[lane + 32*i]; s += v[i]; }
    #pragma unroll
    for (int o = 16; o > 0; o >>= 1) s += __shfl_xor_sync(0xffffffffu, s, o);
    float mean = s * (1.0f/192.0f);
    float vs = 0.f;
    #pragma unroll
    for (int i = 0; i < 6; i++) { v[i] -= mean; vs += v[i]*v[i]; }
    #pragma unroll
    for (int o = 16; o > 0; o >>= 1) vs += __shfl_xor_sync(0xffffffffu, vs, o);
    float inv = rsqrtf(vs * (1.0f/192.0f) + 1e-6f);
    __nv_bfloat16* ph = hi + (size_t)row * 192;
    __nv_bfloat16* pl = lo + (size_t)row * 192;
    #pragma unroll
    for (int i = 0; i < 6; i++) {
        float y = v[i]*inv*g[lane + 32*i] + bb[lane + 32*i];
        __nv_bfloat16 h, l;
        split_bf16(y, h, l);
        ph[lane + 32*i] = h; pl[lane + 32*i] = l;
    }
}

// ---------------- weight convert: W[K,N] fp32 -> [N][K] bf16 hi/lo ---------
__global__ __launch_bounds__(256) void conv_w_kernel(
    const float* __restrict__ W, __nv_bfloat16* __restrict__ hi,
    __nv_bfloat16* __restrict__ lo, int K, int N)
{
    int i = blockIdx.x * 256 + threadIdx.x;
    if (i >= N * K) return;
    int n = i / K, k = i % K;
    float v = W[(size_t)k * N + n];
    __nv_bfloat16 h, l;
    split_bf16(v, h, l);
    hi[i] = h; lo[i] = l;
}

__global__ __launch_bounds__(256) void concat_bias_kernel(
    const float* __restrict__ a, const float* __restrict__ b,
    float* __restrict__ out)
{
    int i = blockIdx.x * 256 + threadIdx.x;
    if (i < 768) out[i] = (i < 192) ? a[i] : b[i - 192];
}

// ---------------- 2x2 maxpool ----------------------------------------------
__global__ __launch_bounds__(256) void pool_kernel(
    const float* __restrict__ p, float* __restrict__ y)
{
    int i = blockIdx.x * 256 + threadIdx.x;
    int c   = i % 192;
    int pix = i / 192;
    int wp = pix & 127, hp = (pix >> 7) & 127, b = pix >> 14;
    size_t base = (((size_t)b*256 + hp*2)*256 + wp*2)*192 + c;
    const size_t rs = 256*192;
    y[i] = fmaxf(fmaxf(p[base], p[base+192]),
                 fmaxf(p[base+rs], p[base+rs+192]));
}

// ---------------- windowed attention (bf16 qkv) -> O (bf16 hi/lo) -----------
#define AQP   0                          // 16*192 = 3072
#define AKH   3072                       // 64*68 (kh[s][d])
#define AVH   (AKH + 64*68)              // 64*68 (vh[d][s])
#define ASC   (AVH + 64*68)              // 16*64
#define ATOT  (ASC + 16*64)              // 12800 floats = 51200 B

__global__ __launch_bounds__(256) void attn_kernel(
    const __nv_bfloat16* __restrict__ qkv,
    __nv_bfloat16* __restrict__ Oh, __nv_bfloat16* __restrict__ Ol)
{
    extern __shared__ float sm[];
    float* qp = sm + AQP;
    float* kh = sm + AKH;
    float* vh = sm + AVH;
    float* sc = sm + ASC;

    int blk = blockIdx.x;
    int b = blk >> 10, wi = (blk >> 5) & 31, wj = blk & 31;
    int tid = threadIdx.x;

    // pooled q (channel pairs)
    for (int i = tid; i < 16*96; i += 256) {
        int t2 = i / 96, cp2 = i % 96;
        int r2 = t2 >> 2, c2 = t2 & 3;
        float m0 = -1e30f, m1 = -1e30f;
        #pragma unroll
        for (int dr = 0; dr < 2; dr++)
            #pragma unroll
            for (int dc = 0; dc < 2; dc++) {
                int row = ((b*256 + wi*8 + r2*2 + dr) << 8) + wj*8 + c2*2 + dc;
                __nv_bfloat162 v = *reinterpret_cast<const __nv_bfloat162*>(
                    &qkv[(size_t)row*576 + cp2*2]);
                m0 = fmaxf(m0, __bfloat162float(v.x));
                m1 = fmaxf(m1, __bfloat162float(v.y));
            }
        qp[t2*192 + cp2*2]     = m0;
        qp[t2*192 + cp2*2 + 1] = m1;
    }

    for (int h = 0; h < 3; h++) {
        __syncthreads();
        for (int i = tid; i < 64*32; i += 256) {
            int dp = i & 31, s = i >> 5;
            int row = ((b*256 + wi*8 + (s >> 3)) << 8) + wj*8 + (s & 7);
            const size_t base = (size_t)row*576 + h*64 + dp*2;
            __nv_bfloat162 kv = *reinterpret_cast<const __nv_bfloat162*>(&qkv[base + 192]);
            __nv_bfloat162 vv = *reinterpret_cast<const __nv_bfloat162*>(&qkv[base + 384]);
            kh[s*68 + dp*2]     = __bfloat162float(kv.x);
            kh[s*68 + dp*2 + 1] = __bfloat162float(kv.y);
            vh[(dp*2)*68 + s]     = __bfloat162float(vv.x);
            vh[(dp*2 + 1)*68 + s] = __bfloat162float(vv.y);
        }
        __syncthreads();
        // scores
        for (int i = tid; i < 16*64; i += 256) {
            int t2 = i >> 6, s = i & 63;
            const float4* qv = reinterpret_cast<const float4*>(&qp[t2*192 + h*64]);
            const float4* kv = reinterpret_cast<const float4*>(&kh[s*68]);
            float acc = 0.f;
            #pragma unroll
            for (int d4 = 0; d4 < 16; d4++) {
                float4 a = qv[d4], bq = kv[d4];
                acc = fmaf(a.x, bq.x, acc);
                acc = fmaf(a.y, bq.y, acc);
                acc = fmaf(a.z, bq.z, acc);
                acc = fmaf(a.w, bq.w, acc);
            }
            sc[i] = acc * 0.125f;
        }
        __syncthreads();
        // softmax per row
        {
            int warp = tid >> 5, lane = tid & 31;
            for (int t2 = warp; t2 < 16; t2 += 8) {
                float v0 = sc[t2*64 + lane], v1 = sc[t2*64 + 32 + lane];
                float mx = fmaxf(v0, v1);
                #pragma unroll
                for (int o = 16; o > 0; o >>= 1)
                    mx = fmaxf(mx, __shfl_xor_sync(0xffffffffu, mx, o));
                float e0 = expf(v0 - mx), e1 = expf(v1 - mx);
                float ss = e0 + e1;
                #pragma unroll
                for (int o = 16; o > 0; o >>= 1)
                    ss += __shfl_xor_sync(0xffffffffu, ss, o);
                float inv = 1.f / ss;
                sc[t2*64 + lane]      = e0 * inv;
                sc[t2*64 + 32 + lane] = e1 * inv;
            }
        }
        __syncthreads();
        // out
        for (int i = tid; i < 16*64; i += 256) {
            int t2 = i >> 6, d = i & 63;
            const float4* pv = reinterpret_cast<const float4*>(&sc[t2*64]);
            const float4* vv = reinterpret_cast<const float4*>(&vh[d*68]);
            float acc = 0.f;
            #pragma unroll
            for (int s4 = 0; s4 < 16; s4++) {
                float4 a = pv[s4], bv = vv[s4];
                acc = fmaf(a.x, bv.x, acc);
                acc = fmaf(a.y, bv.y, acc);
                acc = fmaf(a.z, bv.z, acc);
                acc = fmaf(a.w, bv.w, acc);
            }
            int r2 = t2 >> 2, c2 = t2 & 3;
            size_t orow = ((size_t)(b*128 + wi*4 + r2))*128 + wj*4 + c2;
            __nv_bfloat16 hh, ll;
            split_bf16(acc, hh, ll);
            Oh[orow*192 + h*64 + d] = hh;
            Ol[orow*192 + h*64 + d] = ll;
        }
    }
}

// ---------------- launch ----------------------------------------------------
extern "C" void kernel_launch(void* const* d_in, const int* in_sizes, int n_in,
                              void* d_out, int out_size)
{
    const float* x       = (const float*)d_in[0];
    const float* n1g     = (const float*)d_in[1];
    const float* n1b     = (const float*)d_in[2];
    const float* proj_w  = (const float*)d_in[3];
    const float* proj_b  = (const float*)d_in[4];
    const float* qkv_w   = (const float*)d_in[5];
    const float* qkv_b   = (const float*)d_in[6];
    const float* apw     = (const float*)d_in[7];
    const float* apb     = (const float*)d_in[8];
    const float* n2g     = (const float*)d_in[9];
    const float* n2b     = (const float*)d_in[10];
    const float* w1      = (const float*)d_in[11];
    const float* b1      = (const float*)d_in[12];
    const float* w2      = (const float*)d_in[13];
    const float* b2      = (const float*)d_in[14];
    float* y = (float*)d_out;

    __nv_bfloat16 *xh, *xl, *qkvb, *oh, *ol, *ynh, *ynl, *hh, *hl;
    __nv_bfloat16 *wfh, *wfl, *wah, *wal, *w1h, *w1l, *w2h, *w2l;
    float *proj, *b768;
    cudaGetSymbolAddress((void**)&xh,  g_xh);
    cudaGetSymbolAddress((void**)&xl,  g_xl);
    cudaGetSymbolAddress((void**)&proj, g_proj);
    cudaGetSymbolAddress((void**)&qkvb, g_qkvb);
    cudaGetSymbolAddress((void**)&oh,  g_oh);
    cudaGetSymbolAddress((void**)&ol,  g_ol);
    cudaGetSymbolAddress((void**)&ynh, g_ynh);
    cudaGetSymbolAddress((void**)&ynl, g_ynl);
    cudaGetSymbolAddress((void**)&hh,  g_hh);
    cudaGetSymbolAddress((void**)&hl,  g_hl);
    cudaGetSymbolAddress((void**)&wfh, g_wfh);
    cudaGetSymbolAddress((void**)&wfl, g_wfl);
    cudaGetSymbolAddress((void**)&wah, g_wah);
    cudaGetSymbolAddress((void**)&wal, g_wal);
    cudaGetSymbolAddress((void**)&w1h, g_w1h);
    cudaGetSymbolAddress((void**)&w1l, g_w1l);
    cudaGetSymbolAddress((void**)&w2h, g_w2h);
    cudaGetSymbolAddress((void**)&w2l, g_w2l);
    cudaGetSymbolAddress((void**)&b768, g_b768);

    static bool attr_done = false;
    if (!attr_done) {
        cudaFuncSetAttribute(attn_kernel,
            cudaFuncAttributeMaxDynamicSharedMemorySize, ATOT * 4);
        cudaFuncSetAttribute(gemm_mma,
            cudaFuncAttributeMaxDynamicSharedMemorySize, GEMM_SMEM);
        attr_done = true;
    }

    // weight conversions (tiny)
    conv_w_kernel<<<(192*96+255)/256, 256>>>(proj_w, wfh, wfl, 96, 192);
    conv_w_kernel<<<(576*96+255)/256, 256>>>(qkv_w, wfh + 192*96, wfl + 192*96, 96, 576);
    conv_w_kernel<<<(192*192+255)/256, 256>>>(apw, wah, wal, 192, 192);
    conv_w_kernel<<<(768*192+255)/256, 256>>>(w1, w1h, w1l, 192, 768);
    conv_w_kernel<<<(192*768+255)/256, 256>>>(w2, w2h, w2l, 768, 192);
    concat_bias_kernel<<<3, 256>>>(proj_b, qkv_b, b768);

    // 1) LN1 -> bf16 hi/lo
    ln96b_kernel<<<NPIX/8, 256>>>(x, n1g, n1b, xh, xl);
    // 2) fused proj+qkv GEMM: tile0 -> proj fp32, tiles1-3 -> qkv bf16
    gemm_mma<<<dim3(4, NPIX/128), 256, GEMM_SMEM>>>(
        xh, xl, wfh, wfl, 96, 768, 3, b768, proj, qkvb, nullptr, nullptr);
    // 3) maxpool -> y (shortcut)
    pool_kernel<<<(NPOOL*192)/256, 256>>>(proj, y);
    // 4) windowed attention -> O (bf16 hi/lo)
    attn_kernel<<<NWIN, 256, ATOT * 4>>>(qkvb, oh, ol);
    // 5) attn-proj GEMM: y += O @ apw + apb
    gemm_mma<<<dim3(1, NPOOL/128), 256, GEMM_SMEM>>>(
        oh, ol, wah, wal, 192, 192, 2, apb, y, nullptr, nullptr, y);
    // 6) LN2 -> bf16 hi/lo
    ln192b_kernel<<<NPOOL/8, 256>>>(y, n2g, n2b, ynh, ynl);
    // 7) mlp1 GEMM + gelu -> h (bf16 hi/lo)
    gemm_mma<<<dim3(4, NPOOL/128), 256, GEMM_SMEM>>>(
        ynh, ynl, w1h, w1l, 192, 768, 1, b1, nullptr, hh, hl, nullptr);
    // 8) mlp2 GEMM + residual add -> y (d_out)
    gemm_mma<<<dim3(1, NPOOL/128), 256, GEMM_SMEM>>>(
        hh, hl, w2h, w2l, 768, 192, 2, b2, y, nullptr, nullptr, y);
}

// round 6
// speedup vs baseline: 2.1124x; 1.0109x over previous
#include <cuda_runtime.h>
#include <cuda_bf16.h>
#include <cstdint>
#include <math.h>

// ===========================================================================
// MultiScaleBlock (sm_103 PTX, HMMA mma.sync path).
// Window-major pixel permutation: row = (((b*32+wi)*32+wj)*16 + t2)*4 + dq.
// Fused proj+qkv GEMM with maxpool fused in epilogue (shfl over quad rows).
// bf16 hi/lo x3-product GEMMs; bf16 qkv; windows = 64 contiguous rows.
// ===========================================================================

#define NPIX   (4*256*256)     // 262144
#define NPOOL  (4*128*128)     // 65536
#define NWIN   (4*32*32)       // 4096

// ---------------- scratch (device globals) ----------------------------------
__device__ __nv_bfloat16 g_xh [(size_t)NPIX  * 96];
__device__ __nv_bfloat16 g_xl [(size_t)NPIX  * 96];
__device__ __nv_bfloat16 g_qkvb[(size_t)NPIX * 576];     // bf16 qkv, window-major
__device__ __nv_bfloat16 g_oh [(size_t)NPOOL * 192];
__device__ __nv_bfloat16 g_ol [(size_t)NPOOL * 192];
__device__ __nv_bfloat16 g_ynh[(size_t)NPOOL * 192];
__device__ __nv_bfloat16 g_ynl[(size_t)NPOOL * 192];
__device__ __nv_bfloat16 g_hh [(size_t)NPOOL * 768];
__device__ __nv_bfloat16 g_hl [(size_t)NPOOL * 768];
// weights [N][K] bf16 hi/lo (transposed); proj+qkv fused into 768 rows
__device__ __nv_bfloat16 g_wfh[768*96],  g_wfl[768*96];
__device__ __nv_bfloat16 g_wah[192*192], g_wal[192*192];
__device__ __nv_bfloat16 g_w1h[768*192], g_w1l[768*192];
__device__ __nv_bfloat16 g_w2h[192*768], g_w2l[192*768];
__device__ float         g_b768[768];

// ---------------- helpers ---------------------------------------------------
__device__ __forceinline__ uint32_t smem_u32(const void* p) {
    uint32_t a;
    asm("{ .reg .u64 t; cvta.to.shared.u64 t, %1; cvt.u32.u64 %0, t; }"
        : "=r"(a) : "l"(p));
    return a;
}
__device__ __forceinline__ void cp16(uint32_t s, const void* g) {
    asm volatile("cp.async.ca.shared.global [%0], [%1], 16;"
                 :: "r"(s), "l"(g) : "memory");
}
__device__ __forceinline__ void cp_commit() {
    asm volatile("cp.async.commit_group;" ::: "memory");
}
template<int N>
__device__ __forceinline__ void cp_wait() {
    asm volatile("cp.async.wait_group %0;" :: "n"(N) : "memory");
}
__device__ __forceinline__ void ldsm4(uint32_t* r, uint32_t a) {
    asm volatile("ldmatrix.sync.aligned.m8n8.x4.shared.b16 {%0,%1,%2,%3}, [%4];"
        : "=r"(r[0]), "=r"(r[1]), "=r"(r[2]), "=r"(r[3]) : "r"(a));
}
__device__ __forceinline__ void mma_bf16(float* d, const uint32_t* a,
                                         uint32_t b0, uint32_t b1) {
    asm volatile(
        "mma.sync.aligned.m16n8k16.row.col.f32.bf16.bf16.f32 "
        "{%0,%1,%2,%3}, {%4,%5,%6,%7}, {%8,%9}, {%0,%1,%2,%3};"
        : "+f"(d[0]), "+f"(d[1]), "+f"(d[2]), "+f"(d[3])
        : "r"(a[0]), "r"(a[1]), "r"(a[2]), "r"(a[3]), "r"(b0), "r"(b1));
}
__device__ __forceinline__ void split_bf16(float v, __nv_bfloat16& h, __nv_bfloat16& l) {
    h = __float2bfloat16(v);
    l = __float2bfloat16(v - __bfloat162float(h));
}
__device__ __forceinline__ float gelu_exact(float v) {
    return 0.5f * v * (1.0f + erff(v * 0.70710678118654752f));
}
// window-major quad index -> standard pooled row
__device__ __forceinline__ size_t quad_to_prow(size_t g) {
    int t2 = (int)(g & 15);
    int wj = (int)((g >> 4) & 31);
    int wi = (int)((g >> 9) & 31);
    int b  = (int)(g >> 14);
    return ((size_t)(b * 128 + wi * 4 + (t2 >> 2))) * 128 + wj * 4 + (t2 & 3);
}

// ---------------- HMMA GEMM, BM=128 BN=192 BK=32, 3-stage -------------------
// C = A[M,K] @ B[N,K]^T (bf16 hi/lo x3).
// epi: 1 gelu->bf16 hi/lo; 2 +bias+addsrc fp32;
//      3 fused: bn==0 -> pooled proj into y (fp32 ld192), bn>0 -> qkv bf16 ld576
#define LDA     40                         // BK + 8 (half-words)
#define SA_HI   0
#define SA_LO   (128*LDA*2)                // 10240
#define SB_HI   (2*128*LDA*2)              // 20480
#define SB_LO   (SB_HI + 192*LDA*2)        // 35840
#define STAGE_B (SB_LO + 192*LDA*2)        // 51200
#define GEMM_SMEM (3*STAGE_B)              // 153600

__global__ __launch_bounds__(256, 1) void gemm_mma(
    const __nv_bfloat16* __restrict__ Ah, const __nv_bfloat16* __restrict__ Al,
    const __nv_bfloat16* __restrict__ Bh, const __nv_bfloat16* __restrict__ Bl,
    int K, int N, int epi,
    const float* __restrict__ bias,
    float* __restrict__ Cf,
    __nv_bfloat16* __restrict__ Ch, __nv_bfloat16* __restrict__ Cl,
    const float* __restrict__ addsrc)
{
    extern __shared__ char smem[];
    const uint32_t sb = smem_u32(smem);
    const int tid = threadIdx.x, lane = tid & 31, warp = tid >> 5;
    const int wm = (warp >> 1) * 32;           // 4 warps in M
    const int wn = (warp & 1) * 96;            // 2 warps in N
    const size_t bm = (size_t)blockIdx.y * 128;
    const size_t bn = (size_t)blockIdx.x * 192;
    const int C = K >> 5;

    const __nv_bfloat16* AhB = Ah + bm * K;
    const __nv_bfloat16* AlB = Al + bm * K;
    const __nv_bfloat16* BhB = Bh + bn * K;
    const __nv_bfloat16* BlB = Bl + bn * K;

    float acc[2][12][4];
    #pragma unroll
    for (int i = 0; i < 2; i++)
        #pragma unroll
        for (int j = 0; j < 12; j++)
            #pragma unroll
            for (int q = 0; q < 4; q++) acc[i][j][q] = 0.f;

    auto load_stage = [&](int s, int c) {
        const uint32_t st = sb + (uint32_t)s * STAGE_B;
        const size_t k0 = (size_t)c * 32;
        #pragma unroll
        for (int i = tid; i < 512; i += 256) {       // A: 128 rows x 4 chunks
            int r = i >> 2, q = i & 3;
            uint32_t d = st + (uint32_t)(r * LDA + q * 8) * 2;
            size_t go = (size_t)r * K + k0 + q * 8;
            cp16(d + SA_HI, AhB + go);
            cp16(d + SA_LO, AlB + go);
        }
        #pragma unroll
        for (int i = tid; i < 768; i += 256) {       // B: 192 rows x 4 chunks
            int r = i >> 2, q = i & 3;
            uint32_t d = st + (uint32_t)(r * LDA + q * 8) * 2;
            size_t go = (size_t)r * K + k0 + q * 8;
            cp16(d + SB_HI, BhB + go);
            cp16(d + SB_LO, BlB + go);
        }
        cp_commit();
    };

    auto compute_stage = [&](int s) {
        const uint32_t st = sb + (uint32_t)s * STAGE_B;
        #pragma unroll
        for (int k16 = 0; k16 < 2; k16++) {
            uint32_t ah[2][4], al[2][4];
            #pragma unroll
            for (int mi = 0; mi < 2; mi++) {
                int row = wm + mi * 16 + (lane & 15);
                int col = k16 * 16 + (lane >> 4) * 8;
                uint32_t ad = st + (uint32_t)(row * LDA + col) * 2;
                ldsm4(ah[mi], ad + SA_HI);
                ldsm4(al[mi], ad + SA_LO);
            }
            #pragma unroll
            for (int ng = 0; ng < 6; ng++) {
                uint32_t bh[4], bl[4];
                int nr = wn + ng * 16 + (lane & 7) + ((lane >> 4) & 1) * 8;
                int bc = k16 * 16 + ((lane >> 3) & 1) * 8;
                uint32_t bd = st + (uint32_t)(nr * LDA + bc) * 2;
                ldsm4(bh, bd + SB_HI);
                ldsm4(bl, bd + SB_LO);
                #pragma unroll
                for (int mi = 0; mi < 2; mi++) {
                    #pragma unroll
                    for (int sub = 0; sub < 2; sub++) {
                        float* d = acc[mi][ng * 2 + sub];
                        mma_bf16(d, ah[mi], bh[2*sub], bh[2*sub+1]);
                        mma_bf16(d, ah[mi], bl[2*sub], bl[2*sub+1]);
                        mma_bf16(d, al[mi], bh[2*sub], bh[2*sub+1]);
                    }
                }
            }
        }
    };

    // ---- 3-stage pipeline ----
    load_stage(0, 0);
    load_stage(1, 1);
    for (int c = 0; c < C; c++) {
        if (c + 1 < C) { cp_wait<1>(); } else { cp_wait<0>(); }
        __syncthreads();
        if (c + 2 < C) load_stage((c + 2) % 3, c + 2);
        compute_stage(c % 3);
        __syncthreads();
    }

    // ---- epilogue ----
    #pragma unroll
    for (int mi = 0; mi < 2; mi++) {
        #pragma unroll
        for (int nj = 0; nj < 12; nj++) {
            size_t row0 = bm + wm + mi * 16 + (lane >> 2);
            size_t col  = bn + wn + nj * 8 + 2 * (lane & 3);
            float b0 = bias[col], b1 = bias[col + 1];
            float v00 = acc[mi][nj][0] + b0, v01 = acc[mi][nj][1] + b1;
            float v10 = acc[mi][nj][2] + b0, v11 = acc[mi][nj][3] + b1;
            if (epi == 1) {
                v00 = gelu_exact(v00); v01 = gelu_exact(v01);
                v10 = gelu_exact(v10); v11 = gelu_exact(v11);
                __nv_bfloat16 h, l;
                __nv_bfloat162 hp, lp;
                split_bf16(v00, h, l); hp.x = h; lp.x = l;
                split_bf16(v01, h, l); hp.y = h; lp.y = l;
                *reinterpret_cast<__nv_bfloat162*>(Ch + row0 * N + col) = hp;
                *reinterpret_cast<__nv_bfloat162*>(Cl + row0 * N + col) = lp;
                split_bf16(v10, h, l); hp.x = h; lp.x = l;
                split_bf16(v11, h, l); hp.y = h; lp.y = l;
                *reinterpret_cast<__nv_bfloat162*>(Ch + (row0 + 8) * N + col) = hp;
                *reinterpret_cast<__nv_bfloat162*>(Cl + (row0 + 8) * N + col) = lp;
            } else if (epi == 2) {
                const float2 a0 = *reinterpret_cast<const float2*>(addsrc + row0 * N + col);
                const float2 a1 = *reinterpret_cast<const float2*>(addsrc + (row0 + 8) * N + col);
                *reinterpret_cast<float2*>(Cf + row0 * N + col)       = make_float2(v00 + a0.x, v01 + a0.y);
                *reinterpret_cast<float2*>(Cf + (row0 + 8) * N + col) = make_float2(v10 + a1.x, v11 + a1.y);
            } else {  // epi == 3
                if (bn == 0) {
                    // fused 2x2 maxpool: rows are window-major, quad = 4
                    // consecutive rows; lane groups differing in bits 2-3 of
                    // lane hold the 4 quad rows at the same column pair.
                    float p00 = fmaxf(v00, __shfl_xor_sync(0xffffffffu, v00, 4));
                    p00 = fmaxf(p00, __shfl_xor_sync(0xffffffffu, p00, 8));
                    float p01 = fmaxf(v01, __shfl_xor_sync(0xffffffffu, v01, 4));
                    p01 = fmaxf(p01, __shfl_xor_sync(0xffffffffu, p01, 8));
                    float p10 = fmaxf(v10, __shfl_xor_sync(0xffffffffu, v10, 4));
                    p10 = fmaxf(p10, __shfl_xor_sync(0xffffffffu, p10, 8));
                    float p11 = fmaxf(v11, __shfl_xor_sync(0xffffffffu, v11, 4));
                    p11 = fmaxf(p11, __shfl_xor_sync(0xffffffffu, p11, 8));
                    if ((lane & 12) == 0) {
                        size_t pr0 = quad_to_prow(row0 >> 2);
                        size_t pr1 = quad_to_prow((row0 + 8) >> 2);
                        *reinterpret_cast<float2*>(Cf + pr0 * 192 + col) = make_float2(p00, p01);
                        *reinterpret_cast<float2*>(Cf + pr1 * 192 + col) = make_float2(p10, p11);
                    }
                } else {
                    size_t qc = col - 192;
                    __nv_bfloat162 p0, p1;
                    p0.x = __float2bfloat16(v00); p0.y = __float2bfloat16(v01);
                    p1.x = __float2bfloat16(v10); p1.y = __float2bfloat16(v11);
                    *reinterpret_cast<__nv_bfloat162*>(Ch + row0 * 576 + qc)       = p0;
                    *reinterpret_cast<__nv_bfloat162*>(Ch + (row0 + 8) * 576 + qc) = p1;
                }
            }
        }
    }
}

// ---------------- LN1 -> bf16 hi/lo, window-major permuted rows -------------
__global__ __launch_bounds__(256) void ln96b_kernel(
    const float* __restrict__ x, const float* __restrict__ g,
    const float* __restrict__ bb,
    __nv_bfloat16* __restrict__ hi, __nv_bfloat16* __restrict__ lo)
{
    int row  = blockIdx.x * 8 + (threadIdx.x >> 5);   // source pixel
    int lane = threadIdx.x & 31;
    const float* p = x + (size_t)row * 96;
    float v0 = p[lane], v1 = p[lane+32], v2 = p[lane+64];
    float s = v0 + v1 + v2;
    #pragma unroll
    for (int o = 16; o > 0; o >>= 1) s += __shfl_xor_sync(0xffffffffu, s, o);
    float mean = s * (1.0f/96.0f);
    float d0 = v0-mean, d1 = v1-mean, d2 = v2-mean;
    float vs = d0*d0 + d1*d1 + d2*d2;
    #pragma unroll
    for (int o = 16; o > 0; o >>= 1) vs += __shfl_xor_sync(0xffffffffu, vs, o);
    float inv = rsqrtf(vs * (1.0f/96.0f) + 1e-6f);
    float y0 = d0*inv*g[lane]    + bb[lane];
    float y1 = d1*inv*g[lane+32] + bb[lane+32];
    float y2 = d2*inv*g[lane+64] + bb[lane+64];
    // destination: window-major row
    int wpix = row & 255, hpix = (row >> 8) & 255, b = row >> 16;
    int wi = hpix >> 3, r = hpix & 7, wj = wpix >> 3, c = wpix & 7;
    int t2 = (r >> 1) * 4 + (c >> 1);
    int dq = (r & 1) * 2 + (c & 1);
    size_t wrow = ((((size_t)b * 32 + wi) * 32 + wj) * 16 + t2) * 4 + dq;
    __nv_bfloat16* ph = hi + wrow * 96;
    __nv_bfloat16* pl = lo + wrow * 96;
    __nv_bfloat16 h, l;
    split_bf16(y0, h, l); ph[lane]    = h; pl[lane]    = l;
    split_bf16(y1, h, l); ph[lane+32] = h; pl[lane+32] = l;
    split_bf16(y2, h, l); ph[lane+64] = h; pl[lane+64] = l;
}

__global__ __launch_bounds__(256) void ln192b_kernel(
    const float* __restrict__ x, const float* __restrict__ g,
    const float* __restrict__ bb,
    __nv_bfloat16* __restrict__ hi, __nv_bfloat16* __restrict__ lo)
{
    int row  = blockIdx.x * 8 + (threadIdx.x >> 5);
    int lane = threadIdx.x & 31;
    const float* p = x + (size_t)row * 192;
    float v[6];
    float s = 0.f;
    #pragma unroll
    for (int i = 0; i < 6; i++) { v[i] = p[lane + 32*i]; s += v[i]; }
    #pragma unroll
    for (int o = 16; o > 0; o >>= 1) s += __shfl_xor_sync(0xffffffffu, s, o);
    float mean = s * (1.0f/192.0f);
    float vs = 0.f;
    #pragma unroll
    for (int i = 0; i < 6; i++) { v[i] -= mean; vs += v[i]*v[i]; }
    #pragma unroll
    for (int o = 16; o > 0; o >>= 1) vs += __shfl_xor_sync(0xffffffffu, vs, o);
    float inv = rsqrtf(vs * (1.0f/192.0f) + 1e-6f);
    __nv_bfloat16* ph = hi + (size_t)row * 192;
    __nv_bfloat16* pl = lo + (size_t)row * 192;
    #pragma unroll
    for (int i = 0; i < 6; i++) {
        float y = v[i]*inv*g[lane + 32*i] + bb[lane + 32*i];
        __nv_bfloat16 h, l;
        split_bf16(y, h, l);
        ph[lane + 32*i] = h; pl[lane + 32*i] = l;
    }
}

// ---------------- merged weight conversion + bias concat --------------------
// seg sizes: 18432 | 55296 | 36864 | 147456 | 147456 | 768
__global__ __launch_bounds__(256) void conv_all_kernel(
    const float* __restrict__ proj_w, const float* __restrict__ qkv_w,
    const float* __restrict__ apw, const float* __restrict__ w1,
    const float* __restrict__ w2,
    const float* __restrict__ proj_b, const float* __restrict__ qkv_b,
    __nv_bfloat16* __restrict__ wfh, __nv_bfloat16* __restrict__ wfl,
    __nv_bfloat16* __restrict__ wah, __nv_bfloat16* __restrict__ wal,
    __nv_bfloat16* __restrict__ w1h, __nv_bfloat16* __restrict__ w1l,
    __nv_bfloat16* __restrict__ w2h, __nv_bfloat16* __restrict__ w2l,
    float* __restrict__ b768)
{
    int i = blockIdx.x * 256 + threadIdx.x;
    const float* W; __nv_bfloat16 *H, *L;
    int K, N, j;
    if (i < 18432)        { W = proj_w; H = wfh;            L = wfl;            K = 96;  N = 192; j = i; }
    else if (i < 73728)   { W = qkv_w;  H = wfh + 18432;    L = wfl + 18432;    K = 96;  N = 576; j = i - 18432; }
    else if (i < 110592)  { W = apw;    H = wah;            L = wal;            K = 192; N = 192; j = i - 73728; }
    else if (i < 258048)  { W = w1;     H = w1h;            L = w1l;            K = 192; N = 768; j = i - 110592; }
    else if (i < 405504)  { W = w2;     H = w2h;            L = w2l;            K = 768; N = 192; j = i - 258048; }
    else if (i < 406272)  { j = i - 405504; b768[j] = (j < 192) ? proj_b[j] : qkv_b[j - 192]; return; }
    else return;
    int n = j / K, k = j % K;
    float v = W[(size_t)k * N + n];
    __nv_bfloat16 h, l;
    split_bf16(v, h, l);
    H[j] = h; L[j] = l;
}

// ---------------- windowed attention (window-major bf16 qkv) ----------------
#define AQP   0                          // 16*192 = 3072
#define AKH   3072                       // 64*68 (kh[s][d])
#define AVH   (AKH + 64*68)              // 64*68 (vh[d][s])
#define ASC   (AVH + 64*68)              // 16*64
#define ATOT  (ASC + 16*64)              // 12800 floats = 51200 B

__global__ __launch_bounds__(256) void attn_kernel(
    const __nv_bfloat16* __restrict__ qkv,
    __nv_bfloat16* __restrict__ Oh, __nv_bfloat16* __restrict__ Ol)
{
    extern __shared__ float sm[];
    float* qp = sm + AQP;
    float* kh = sm + AKH;
    float* vh = sm + AVH;
    float* sc = sm + ASC;

    int w = blockIdx.x;                      // window index
    int b = w >> 10, wi = (w >> 5) & 31, wj = w & 31;
    int tid = threadIdx.x;
    const __nv_bfloat16* base = qkv + (size_t)w * 64 * 576;

    // pooled q: quad t2 = rows 4*t2..4*t2+3 (contiguous)
    for (int i = tid; i < 16*96; i += 256) {
        int t2 = i / 96, cp2 = i % 96;
        float m0 = -1e30f, m1 = -1e30f;
        #pragma unroll
        for (int dq = 0; dq < 4; dq++) {
            __nv_bfloat162 v = *reinterpret_cast<const __nv_bfloat162*>(
                &base[(size_t)(t2*4 + dq)*576 + cp2*2]);
            m0 = fmaxf(m0, __bfloat162float(v.x));
            m1 = fmaxf(m1, __bfloat162float(v.y));
        }
        qp[t2*192 + cp2*2]     = m0;
        qp[t2*192 + cp2*2 + 1] = m1;
    }

    for (int h = 0; h < 3; h++) {
        __syncthreads();
        for (int i = tid; i < 64*32; i += 256) {
            int dp = i & 31, s = i >> 5;
            const size_t off = (size_t)s*576 + h*64 + dp*2;
            __nv_bfloat162 kv = *reinterpret_cast<const __nv_bfloat162*>(&base[off + 192]);
            __nv_bfloat162 vv = *reinterpret_cast<const __nv_bfloat162*>(&base[off + 384]);
            kh[s*68 + dp*2]     = __bfloat162float(kv.x);
            kh[s*68 + dp*2 + 1] = __bfloat162float(kv.y);
            vh[(dp*2)*68 + s]     = __bfloat162float(vv.x);
            vh[(dp*2 + 1)*68 + s] = __bfloat162float(vv.y);
        }
        __syncthreads();
        // scores
        for (int i = tid; i < 16*64; i += 256) {
            int t2 = i >> 6, s = i & 63;
            const float4* qv = reinterpret_cast<const float4*>(&qp[t2*192 + h*64]);
            const float4* kv = reinterpret_cast<const float4*>(&kh[s*68]);
            float acc = 0.f;
            #pragma unroll
            for (int d4 = 0; d4 < 16; d4++) {
                float4 a = qv[d4], bq = kv[d4];
                acc = fmaf(a.x, bq.x, acc);
                acc = fmaf(a.y, bq.y, acc);
                acc = fmaf(a.z, bq.z, acc);
                acc = fmaf(a.w, bq.w, acc);
            }
            sc[i] = acc * 0.125f;
        }
        __syncthreads();
        // softmax per row
        {
            int warp = tid >> 5, lane = tid & 31;
            for (int t2 = warp; t2 < 16; t2 += 8) {
                float v0 = sc[t2*64 + lane], v1 = sc[t2*64 + 32 + lane];
                float mx = fmaxf(v0, v1);
                #pragma unroll
                for (int o = 16; o > 0; o >>= 1)
                    mx = fmaxf(mx, __shfl_xor_sync(0xffffffffu, mx, o));
                float e0 = expf(v0 - mx), e1 = expf(v1 - mx);
                float ss = e0 + e1;
                #pragma unroll
                for (int o = 16; o > 0; o >>= 1)
                    ss += __shfl_xor_sync(0xffffffffu, ss, o);
                float inv = 1.f / ss;
                sc[t2*64 + lane]      = e0 * inv;
                sc[t2*64 + 32 + lane] = e1 * inv;
            }
        }
        __syncthreads();
        // out
        for (int i = tid; i < 16*64; i += 256) {
            int t2 = i >> 6, d = i & 63;
            const float4* pv = reinterpret_cast<const float4*>(&sc[t2*64]);
            const float4* vv = reinterpret_cast<const float4*>(&vh[d*68]);
            float acc = 0.f;
            #pragma unroll
            for (int s4 = 0; s4 < 16; s4++) {
                float4 a = pv[s4], bv = vv[s4];
                acc = fmaf(a.x, bv.x, acc);
                acc = fmaf(a.y, bv.y, acc);
                acc = fmaf(a.z, bv.z, acc);
                acc = fmaf(a.w, bv.w, acc);
            }
            size_t orow = ((size_t)(b*128 + wi*4 + (t2 >> 2)))*128 + wj*4 + (t2 & 3);
            __nv_bfloat16 hh, ll;
            split_bf16(acc, hh, ll);
            Oh[orow*192 + h*64 + d] = hh;
            Ol[orow*192 + h*64 + d] = ll;
        }
    }
}

// ---------------- launch ----------------------------------------------------
extern "C" void kernel_launch(void* const* d_in, const int* in_sizes, int n_in,
                              void* d_out, int out_size)
{
    const float* x       = (const float*)d_in[0];
    const float* n1g     = (const float*)d_in[1];
    const float* n1b     = (const float*)d_in[2];
    const float* proj_w  = (const float*)d_in[3];
    const float* proj_b  = (const float*)d_in[4];
    const float* qkv_w   = (const float*)d_in[5];
    const float* qkv_b   = (const float*)d_in[6];
    const float* apw     = (const float*)d_in[7];
    const float* apb     = (const float*)d_in[8];
    const float* n2g     = (const float*)d_in[9];
    const float* n2b     = (const float*)d_in[10];
    const float* w1      = (const float*)d_in[11];
    const float* b1      = (const float*)d_in[12];
    const float* w2      = (const float*)d_in[13];
    const float* b2      = (const float*)d_in[14];
    float* y = (float*)d_out;

    __nv_bfloat16 *xh, *xl, *qkvb, *oh, *ol, *ynh, *ynl, *hh, *hl;
    __nv_bfloat16 *wfh, *wfl, *wah, *wal, *w1h, *w1l, *w2h, *w2l;
    float *b768;
    cudaGetSymbolAddress((void**)&xh,  g_xh);
    cudaGetSymbolAddress((void**)&xl,  g_xl);
    cudaGetSymbolAddress((void**)&qkvb, g_qkvb);
    cudaGetSymbolAddress((void**)&oh,  g_oh);
    cudaGetSymbolAddress((void**)&ol,  g_ol);
    cudaGetSymbolAddress((void**)&ynh, g_ynh);
    cudaGetSymbolAddress((void**)&ynl, g_ynl);
    cudaGetSymbolAddress((void**)&hh,  g_hh);
    cudaGetSymbolAddress((void**)&hl,  g_hl);
    cudaGetSymbolAddress((void**)&wfh, g_wfh);
    cudaGetSymbolAddress((void**)&wfl, g_wfl);
    cudaGetSymbolAddress((void**)&wah, g_wah);
    cudaGetSymbolAddress((void**)&wal, g_wal);
    cudaGetSymbolAddress((void**)&w1h, g_w1h);
    cudaGetSymbolAddress((void**)&w1l, g_w1l);
    cudaGetSymbolAddress((void**)&w2h, g_w2h);
    cudaGetSymbolAddress((void**)&w2l, g_w2l);
    cudaGetSymbolAddress((void**)&b768, g_b768);

    static bool attr_done = false;
    if (!attr_done) {
        cudaFuncSetAttribute(attn_kernel,
            cudaFuncAttributeMaxDynamicSharedMemorySize, ATOT * 4);
        cudaFuncSetAttribute(gemm_mma,
            cudaFuncAttributeMaxDynamicSharedMemorySize, GEMM_SMEM);
        attr_done = true;
    }

    // 0) merged weight conversions + bias concat
    conv_all_kernel<<<(406272 + 255) / 256, 256>>>(
        proj_w, qkv_w, apw, w1, w2, proj_b, qkv_b,
        wfh, wfl, wah, wal, w1h, w1l, w2h, w2l, b768);
    // 1) LN1 -> bf16 hi/lo (window-major rows)
    ln96b_kernel<<<NPIX/8, 256>>>(x, n1g, n1b, xh, xl);
    // 2) fused proj+qkv GEMM: tile0 -> pooled y, tiles1-3 -> qkv bf16
    gemm_mma<<<dim3(4, NPIX/128), 256, GEMM_SMEM>>>(
        xh, xl, wfh, wfl, 96, 768, 3, b768, y, qkvb, nullptr, nullptr);
    // 3) windowed attention -> O (bf16 hi/lo)
    attn_kernel<<<NWIN, 256, ATOT * 4>>>(qkvb, oh, ol);
    // 4) attn-proj GEMM: y += O @ apw + apb
    gemm_mma<<<dim3(1, NPOOL/128), 256, GEMM_SMEM>>>(
        oh, ol, wah, wal, 192, 192, 2, apb, y, nullptr, nullptr, y);
    // 5) LN2 -> bf16 hi/lo
    ln192b_kernel<<<NPOOL/8, 256>>>(y, n2g, n2b, ynh, ynl);
    // 6) mlp1 GEMM + gelu -> h (bf16 hi/lo)
    gemm_mma<<<dim3(4, NPOOL/128), 256, GEMM_SMEM>>>(
        ynh, ynl, w1h, w1l, 192, 768, 1, b1, nullptr, hh, hl, nullptr);
    // 7) mlp2 GEMM + residual add -> y (d_out)
    gemm_mma<<<dim3(1, NPOOL/128), 256, GEMM_SMEM>>>(
        hh, hl, w2h, w2l, 768, 192, 2, b2, y, nullptr, nullptr, y);
}

// round 7
// speedup vs baseline: 2.2527x; 1.0664x over previous
#include <cuda_runtime.h>
#include <cuda_bf16.h>
#include <cstdint>
#include <math.h>

// ===========================================================================
// MultiScaleBlock (sm_103 PTX, HMMA mma.sync path).
// Window-major pixel permutation: row = (((b*32+wi)*32+wj)*16 + t2)*4 + dq.
// Fused proj+qkv GEMM with maxpool fused in epilogue.
// Attention: bf16x2-packed smem + 4x4 register blocking, all heads parallel.
// ===========================================================================

#define NPIX   (4*256*256)     // 262144
#define NPOOL  (4*128*128)     // 65536
#define NWIN   (4*32*32)       // 4096

// ---------------- scratch (device globals) ----------------------------------
__device__ __nv_bfloat16 g_xh [(size_t)NPIX  * 96];
__device__ __nv_bfloat16 g_xl [(size_t)NPIX  * 96];
__device__ __nv_bfloat16 g_qkvb[(size_t)NPIX * 576];     // bf16 qkv, window-major
__device__ __nv_bfloat16 g_oh [(size_t)NPOOL * 192];
__device__ __nv_bfloat16 g_ol [(size_t)NPOOL * 192];
__device__ __nv_bfloat16 g_ynh[(size_t)NPOOL * 192];
__device__ __nv_bfloat16 g_ynl[(size_t)NPOOL * 192];
__device__ __nv_bfloat16 g_hh [(size_t)NPOOL * 768];
__device__ __nv_bfloat16 g_hl [(size_t)NPOOL * 768];
// weights [N][K] bf16 hi/lo (transposed); proj+qkv fused into 768 rows
__device__ __nv_bfloat16 g_wfh[768*96],  g_wfl[768*96];
__device__ __nv_bfloat16 g_wah[192*192], g_wal[192*192];
__device__ __nv_bfloat16 g_w1h[768*192], g_w1l[768*192];
__device__ __nv_bfloat16 g_w2h[192*768], g_w2l[192*768];
__device__ float         g_b768[768];

// ---------------- helpers ---------------------------------------------------
__device__ __forceinline__ uint32_t smem_u32(const void* p) {
    uint32_t a;
    asm("{ .reg .u64 t; cvta.to.shared.u64 t, %1; cvt.u32.u64 %0, t; }"
        : "=r"(a) : "l"(p));
    return a;
}
__device__ __forceinline__ void cp16(uint32_t s, const void* g) {
    asm volatile("cp.async.ca.shared.global [%0], [%1], 16;"
                 :: "r"(s), "l"(g) : "memory");
}
__device__ __forceinline__ void cp_commit() {
    asm volatile("cp.async.commit_group;" ::: "memory");
}
template<int N>
__device__ __forceinline__ void cp_wait() {
    asm volatile("cp.async.wait_group %0;" :: "n"(N) : "memory");
}
__device__ __forceinline__ void ldsm4(uint32_t* r, uint32_t a) {
    asm volatile("ldmatrix.sync.aligned.m8n8.x4.shared.b16 {%0,%1,%2,%3}, [%4];"
        : "=r"(r[0]), "=r"(r[1]), "=r"(r[2]), "=r"(r[3]) : "r"(a));
}
__device__ __forceinline__ void mma_bf16(float* d, const uint32_t* a,
                                         uint32_t b0, uint32_t b1) {
    asm volatile(
        "mma.sync.aligned.m16n8k16.row.col.f32.bf16.bf16.f32 "
        "{%0,%1,%2,%3}, {%4,%5,%6,%7}, {%8,%9}, {%0,%1,%2,%3};"
        : "+f"(d[0]), "+f"(d[1]), "+f"(d[2]), "+f"(d[3])
        : "r"(a[0]), "r"(a[1]), "r"(a[2]), "r"(a[3]), "r"(b0), "r"(b1));
}
__device__ __forceinline__ void split_bf16(float v, __nv_bfloat16& h, __nv_bfloat16& l) {
    h = __float2bfloat16(v);
    l = __float2bfloat16(v - __bfloat162float(h));
}
__device__ __forceinline__ float gelu_exact(float v) {
    return 0.5f * v * (1.0f + erff(v * 0.70710678118654752f));
}
// window-major quad index -> standard pooled row
__device__ __forceinline__ size_t quad_to_prow(size_t g) {
    int t2 = (int)(g & 15);
    int wj = (int)((g >> 4) & 31);
    int wi = (int)((g >> 9) & 31);
    int b  = (int)(g >> 14);
    return ((size_t)(b * 128 + wi * 4 + (t2 >> 2))) * 128 + wj * 4 + (t2 & 3);
}

// ---------------- HMMA GEMM, BM=128 BN=192 BK=32, 3-stage -------------------
#define LDA     40                         // BK + 8 (half-words)
#define SA_HI   0
#define SA_LO   (128*LDA*2)                // 10240
#define SB_HI   (2*128*LDA*2)              // 20480
#define SB_LO   (SB_HI + 192*LDA*2)        // 35840
#define STAGE_B (SB_LO + 192*LDA*2)        // 51200
#define GEMM_SMEM (3*STAGE_B)              // 153600

__global__ __launch_bounds__(256, 1) void gemm_mma(
    const __nv_bfloat16* __restrict__ Ah, const __nv_bfloat16* __restrict__ Al,
    const __nv_bfloat16* __restrict__ Bh, const __nv_bfloat16* __restrict__ Bl,
    int K, int N, int epi,
    const float* __restrict__ bias,
    float* __restrict__ Cf,
    __nv_bfloat16* __restrict__ Ch, __nv_bfloat16* __restrict__ Cl,
    const float* __restrict__ addsrc)
{
    extern __shared__ char smem[];
    const uint32_t sb = smem_u32(smem);
    const int tid = threadIdx.x, lane = tid & 31, warp = tid >> 5;
    const int wm = (warp >> 1) * 32;           // 4 warps in M
    const int wn = (warp & 1) * 96;            // 2 warps in N
    const size_t bm = (size_t)blockIdx.y * 128;
    const size_t bn = (size_t)blockIdx.x * 192;
    const int C = K >> 5;

    const __nv_bfloat16* AhB = Ah + bm * K;
    const __nv_bfloat16* AlB = Al + bm * K;
    const __nv_bfloat16* BhB = Bh + bn * K;
    const __nv_bfloat16* BlB = Bl + bn * K;

    float acc[2][12][4];
    #pragma unroll
    for (int i = 0; i < 2; i++)
        #pragma unroll
        for (int j = 0; j < 12; j++)
            #pragma unroll
            for (int q = 0; q < 4; q++) acc[i][j][q] = 0.f;

    auto load_stage = [&](int s, int c) {
        const uint32_t st = sb + (uint32_t)s * STAGE_B;
        const size_t k0 = (size_t)c * 32;
        #pragma unroll
        for (int i = tid; i < 512; i += 256) {       // A: 128 rows x 4 chunks
            int r = i >> 2, q = i & 3;
            uint32_t d = st + (uint32_t)(r * LDA + q * 8) * 2;
            size_t go = (size_t)r * K + k0 + q * 8;
            cp16(d + SA_HI, AhB + go);
            cp16(d + SA_LO, AlB + go);
        }
        #pragma unroll
        for (int i = tid; i < 768; i += 256) {       // B: 192 rows x 4 chunks
            int r = i >> 2, q = i & 3;
            uint32_t d = st + (uint32_t)(r * LDA + q * 8) * 2;
            size_t go = (size_t)r * K + k0 + q * 8;
            cp16(d + SB_HI, BhB + go);
            cp16(d + SB_LO, BlB + go);
        }
        cp_commit();
    };

    auto compute_stage = [&](int s) {
        const uint32_t st = sb + (uint32_t)s * STAGE_B;
        #pragma unroll
        for (int k16 = 0; k16 < 2; k16++) {
            uint32_t ah[2][4], al[2][4];
            #pragma unroll
            for (int mi = 0; mi < 2; mi++) {
                int row = wm + mi * 16 + (lane & 15);
                int col = k16 * 16 + (lane >> 4) * 8;
                uint32_t ad = st + (uint32_t)(row * LDA + col) * 2;
                ldsm4(ah[mi], ad + SA_HI);
                ldsm4(al[mi], ad + SA_LO);
            }
            #pragma unroll
            for (int ng = 0; ng < 6; ng++) {
                uint32_t bh[4], bl[4];
                int nr = wn + ng * 16 + (lane & 7) + ((lane >> 4) & 1) * 8;
                int bc = k16 * 16 + ((lane >> 3) & 1) * 8;
                uint32_t bd = st + (uint32_t)(nr * LDA + bc) * 2;
                ldsm4(bh, bd + SB_HI);
                ldsm4(bl, bd + SB_LO);
                #pragma unroll
                for (int mi = 0; mi < 2; mi++) {
                    #pragma unroll
                    for (int sub = 0; sub < 2; sub++) {
                        float* d = acc[mi][ng * 2 + sub];
                        mma_bf16(d, ah[mi], bh[2*sub], bh[2*sub+1]);
                        mma_bf16(d, ah[mi], bl[2*sub], bl[2*sub+1]);
                        mma_bf16(d, al[mi], bh[2*sub], bh[2*sub+1]);
                    }
                }
            }
        }
    };

    // ---- 3-stage pipeline ----
    load_stage(0, 0);
    load_stage(1, 1);
    for (int c = 0; c < C; c++) {
        if (c + 1 < C) { cp_wait<1>(); } else { cp_wait<0>(); }
        __syncthreads();
        if (c + 2 < C) load_stage((c + 2) % 3, c + 2);
        compute_stage(c % 3);
        __syncthreads();
    }

    // ---- epilogue ----
    #pragma unroll
    for (int mi = 0; mi < 2; mi++) {
        #pragma unroll
        for (int nj = 0; nj < 12; nj++) {
            size_t row0 = bm + wm + mi * 16 + (lane >> 2);
            size_t col  = bn + wn + nj * 8 + 2 * (lane & 3);
            float b0 = bias[col], b1 = bias[col + 1];
            float v00 = acc[mi][nj][0] + b0, v01 = acc[mi][nj][1] + b1;
            float v10 = acc[mi][nj][2] + b0, v11 = acc[mi][nj][3] + b1;
            if (epi == 1) {
                v00 = gelu_exact(v00); v01 = gelu_exact(v01);
                v10 = gelu_exact(v10); v11 = gelu_exact(v11);
                __nv_bfloat16 h, l;
                __nv_bfloat162 hp, lp;
                split_bf16(v00, h, l); hp.x = h; lp.x = l;
                split_bf16(v01, h, l); hp.y = h; lp.y = l;
                *reinterpret_cast<__nv_bfloat162*>(Ch + row0 * N + col) = hp;
                *reinterpret_cast<__nv_bfloat162*>(Cl + row0 * N + col) = lp;
                split_bf16(v10, h, l); hp.x = h; lp.x = l;
                split_bf16(v11, h, l); hp.y = h; lp.y = l;
                *reinterpret_cast<__nv_bfloat162*>(Ch + (row0 + 8) * N + col) = hp;
                *reinterpret_cast<__nv_bfloat162*>(Cl + (row0 + 8) * N + col) = lp;
            } else if (epi == 2) {
                const float2 a0 = *reinterpret_cast<const float2*>(addsrc + row0 * N + col);
                const float2 a1 = *reinterpret_cast<const float2*>(addsrc + (row0 + 8) * N + col);
                *reinterpret_cast<float2*>(Cf + row0 * N + col)       = make_float2(v00 + a0.x, v01 + a0.y);
                *reinterpret_cast<float2*>(Cf + (row0 + 8) * N + col) = make_float2(v10 + a1.x, v11 + a1.y);
            } else {  // epi == 3
                if (bn == 0) {
                    float p00 = fmaxf(v00, __shfl_xor_sync(0xffffffffu, v00, 4));
                    p00 = fmaxf(p00, __shfl_xor_sync(0xffffffffu, p00, 8));
                    float p01 = fmaxf(v01, __shfl_xor_sync(0xffffffffu, v01, 4));
                    p01 = fmaxf(p01, __shfl_xor_sync(0xffffffffu, p01, 8));
                    float p10 = fmaxf(v10, __shfl_xor_sync(0xffffffffu, v10, 4));
                    p10 = fmaxf(p10, __shfl_xor_sync(0xffffffffu, p10, 8));
                    float p11 = fmaxf(v11, __shfl_xor_sync(0xffffffffu, v11, 4));
                    p11 = fmaxf(p11, __shfl_xor_sync(0xffffffffu, p11, 8));
                    if ((lane & 12) == 0) {
                        size_t pr0 = quad_to_prow(row0 >> 2);
                        size_t pr1 = quad_to_prow((row0 + 8) >> 2);
                        *reinterpret_cast<float2*>(Cf + pr0 * 192 + col) = make_float2(p00, p01);
                        *reinterpret_cast<float2*>(Cf + pr1 * 192 + col) = make_float2(p10, p11);
                    }
                } else {
                    size_t qc = col - 192;
                    __nv_bfloat162 p0, p1;
                    p0.x = __float2bfloat16(v00); p0.y = __float2bfloat16(v01);
                    p1.x = __float2bfloat16(v10); p1.y = __float2bfloat16(v11);
                    *reinterpret_cast<__nv_bfloat162*>(Ch + row0 * 576 + qc)       = p0;
                    *reinterpret_cast<__nv_bfloat162*>(Ch + (row0 + 8) * 576 + qc) = p1;
                }
            }
        }
    }
}

// ---------------- LN1 -> bf16 hi/lo, window-major permuted rows -------------
__global__ __launch_bounds__(256) void ln96b_kernel(
    const float* __restrict__ x, const float* __restrict__ g,
    const float* __restrict__ bb,
    __nv_bfloat16* __restrict__ hi, __nv_bfloat16* __restrict__ lo)
{
    int row  = blockIdx.x * 8 + (threadIdx.x >> 5);   // source pixel
    int lane = threadIdx.x & 31;
    const float* p = x + (size_t)row * 96;
    float v0 = p[lane], v1 = p[lane+32], v2 = p[lane+64];
    float s = v0 + v1 + v2;
    #pragma unroll
    for (int o = 16; o > 0; o >>= 1) s += __shfl_xor_sync(0xffffffffu, s, o);
    float mean = s * (1.0f/96.0f);
    float d0 = v0-mean, d1 = v1-mean, d2 = v2-mean;
    float vs = d0*d0 + d1*d1 + d2*d2;
    #pragma unroll
    for (int o = 16; o > 0; o >>= 1) vs += __shfl_xor_sync(0xffffffffu, vs, o);
    float inv = rsqrtf(vs * (1.0f/96.0f) + 1e-6f);
    float y0 = d0*inv*g[lane]    + bb[lane];
    float y1 = d1*inv*g[lane+32] + bb[lane+32];
    float y2 = d2*inv*g[lane+64] + bb[lane+64];
    int wpix = row & 255, hpix = (row >> 8) & 255, b = row >> 16;
    int wi = hpix >> 3, r = hpix & 7, wj = wpix >> 3, c = wpix & 7;
    int t2 = (r >> 1) * 4 + (c >> 1);
    int dq = (r & 1) * 2 + (c & 1);
    size_t wrow = ((((size_t)b * 32 + wi) * 32 + wj) * 16 + t2) * 4 + dq;
    __nv_bfloat16* ph = hi + wrow * 96;
    __nv_bfloat16* pl = lo + wrow * 96;
    __nv_bfloat16 h, l;
    split_bf16(y0, h, l); ph[lane]    = h; pl[lane]    = l;
    split_bf16(y1, h, l); ph[lane+32] = h; pl[lane+32] = l;
    split_bf16(y2, h, l); ph[lane+64] = h; pl[lane+64] = l;
}

__global__ __launch_bounds__(256) void ln192b_kernel(
    const float* __restrict__ x, const float* __restrict__ g,
    const float* __restrict__ bb,
    __nv_bfloat16* __restrict__ hi, __nv_bfloat16* __restrict__ lo)
{
    int row  = blockIdx.x * 8 + (threadIdx.x >> 5);
    int lane = threadIdx.x & 31;
    const float* p = x + (size_t)row * 192;
    float v[6];
    float s = 0.f;
    #pragma unroll
    for (int i = 0; i < 6; i++) { v[i] = p[lane + 32*i]; s += v[i]; }
    #pragma unroll
    for (int o = 16; o > 0; o >>= 1) s += __shfl_xor_sync(0xffffffffu, s, o);
    float mean = s * (1.0f/192.0f);
    float vs = 0.f;
    #pragma unroll
    for (int i = 0; i < 6; i++) { v[i] -= mean; vs += v[i]*v[i]; }
    #pragma unroll
    for (int o = 16; o > 0; o >>= 1) vs += __shfl_xor_sync(0xffffffffu, vs, o);
    float inv = rsqrtf(vs * (1.0f/192.0f) + 1e-6f);
    __nv_bfloat16* ph = hi + (size_t)row * 192;
    __nv_bfloat16* pl = lo + (size_t)row * 192;
    #pragma unroll
    for (int i = 0; i < 6; i++) {
        float y = v[i]*inv*g[lane + 32*i] + bb[lane + 32*i];
        __nv_bfloat16 h, l;
        split_bf16(y, h, l);
        ph[lane + 32*i] = h; pl[lane + 32*i] = l;
    }
}

// ---------------- merged weight conversion + bias concat --------------------
__global__ __launch_bounds__(256) void conv_all_kernel(
    const float* __restrict__ proj_w, const float* __restrict__ qkv_w,
    const float* __restrict__ apw, const float* __restrict__ w1,
    const float* __restrict__ w2,
    const float* __restrict__ proj_b, const float* __restrict__ qkv_b,
    __nv_bfloat16* __restrict__ wfh, __nv_bfloat16* __restrict__ wfl,
    __nv_bfloat16* __restrict__ wah, __nv_bfloat16* __restrict__ wal,
    __nv_bfloat16* __restrict__ w1h, __nv_bfloat16* __restrict__ w1l,
    __nv_bfloat16* __restrict__ w2h, __nv_bfloat16* __restrict__ w2l,
    float* __restrict__ b768)
{
    int i = blockIdx.x * 256 + threadIdx.x;
    const float* W; __nv_bfloat16 *H, *L;
    int K, N, j;
    if (i < 18432)        { W = proj_w; H = wfh;            L = wfl;            K = 96;  N = 192; j = i; }
    else if (i < 73728)   { W = qkv_w;  H = wfh + 18432;    L = wfl + 18432;    K = 96;  N = 576; j = i - 18432; }
    else if (i < 110592)  { W = apw;    H = wah;            L = wal;            K = 192; N = 192; j = i - 73728; }
    else if (i < 258048)  { W = w1;     H = w1h;            L = w1l;            K = 192; N = 768; j = i - 110592; }
    else if (i < 405504)  { W = w2;     H = w2h;            L = w2l;            K = 768; N = 192; j = i - 258048; }
    else if (i < 406272)  { j = i - 405504; b768[j] = (j < 192) ? proj_b[j] : qkv_b[j - 192]; return; }
    else return;
    int n = j / K, k = j % K;
    float v = W[(size_t)k * N + n];
    __nv_bfloat16 h, l;
    split_bf16(v, h, l);
    H[j] = h; L[j] = l;
}

// ---------------- windowed attention: packed bf16x2, 4x4 reg blocking -------
// smem (words): qp [16][100] @0 | kh [3][64][35] @1600 | vh bf16 [3][64][66]
// @8320w | sc fp32 [3][16][64] @14656w ; total 17728 words = 70912 B
#define ATT_SMEM 70912

__global__ __launch_bounds__(256, 2) void attn_kernel(
    const __nv_bfloat16* __restrict__ qkv,
    __nv_bfloat16* __restrict__ Oh, __nv_bfloat16* __restrict__ Ol)
{
    extern __shared__ float sm[];
    uint32_t* qp = reinterpret_cast<uint32_t*>(sm);                    // [16][100]
    uint32_t* kh = qp + 1600;                                          // [3][64][35]
    __nv_bfloat16* vh = reinterpret_cast<__nv_bfloat16*>(kh + 6720);   // [3][64][66]
    float* sc = sm + 14656;                                            // [3][16][64]

    int w = blockIdx.x;
    int b = w >> 10, wi = (w >> 5) & 31, wj = w & 31;
    int tid = threadIdx.x;
    const uint32_t* qk = reinterpret_cast<const uint32_t*>(qkv + (size_t)w * 64 * 576);

    // 1) pooled q (bf16-exact max), packed bf16x2
    for (int i = tid; i < 16*96; i += 256) {
        int t2 = i / 96, c2 = i % 96;
        float m0 = -1e30f, m1 = -1e30f;
        #pragma unroll
        for (int dq = 0; dq < 4; dq++) {
            uint32_t wd = qk[(t2*4 + dq)*288 + c2];
            __nv_bfloat162 v = *reinterpret_cast<__nv_bfloat162*>(&wd);
            m0 = fmaxf(m0, __bfloat162float(v.x));
            m1 = fmaxf(m1, __bfloat162float(v.y));
        }
        __nv_bfloat162 r;
        r.x = __float2bfloat16(m0); r.y = __float2bfloat16(m1);
        qp[t2*100 + c2] = *reinterpret_cast<uint32_t*>(&r);
    }
    // 2) k packed rows; v transposed to [d][s] bf16
    for (int i = tid; i < 3*64*32; i += 256) {
        int d2 = i & 31, s = (i >> 5) & 63, h = i >> 11;
        kh[(h*64 + s)*35 + d2] = qk[s*288 + 96 + h*32 + d2];
        uint32_t vw = qk[s*288 + 192 + h*32 + d2];
        __nv_bfloat162 vv = *reinterpret_cast<__nv_bfloat162*>(&vw);
        vh[(h*64 + d2*2    )*66 + s] = vv.x;
        vh[(h*64 + d2*2 + 1)*66 + s] = vv.y;
    }
    __syncthreads();

    // 3) scores: 192 threads, 4 t2-rows x 4 keys each
    if (tid < 192) {
        int sg = tid & 15, tg = (tid >> 4) & 3, h = tid >> 6;
        float acc[4][4] = {};
        #pragma unroll 4
        for (int d2 = 0; d2 < 32; d2++) {
            float2 qv[4], kv[4];
            #pragma unroll
            for (int i = 0; i < 4; i++) {
                uint32_t qw = qp[(tg*4 + i)*100 + h*32 + d2];
                qv[i] = __bfloat1622float2(*reinterpret_cast<__nv_bfloat162*>(&qw));
                uint32_t kw = kh[(h*64 + sg*4 + i)*35 + d2];
                kv[i] = __bfloat1622float2(*reinterpret_cast<__nv_bfloat162*>(&kw));
            }
            #pragma unroll
            for (int i = 0; i < 4; i++)
                #pragma unroll
                for (int j = 0; j < 4; j++) {
                    acc[i][j] = fmaf(qv[i].x, kv[j].x, acc[i][j]);
                    acc[i][j] = fmaf(qv[i].y, kv[j].y, acc[i][j]);
                }
        }
        #pragma unroll
        for (int i = 0; i < 4; i++)
            #pragma unroll
            for (int j = 0; j < 4; j++)
                sc[(h*16 + tg*4 + i)*64 + sg*4 + j] = acc[i][j] * 0.125f;
    }
    __syncthreads();

    // 4) softmax: 48 rows over 8 warps
    {
        int warp = tid >> 5, lane = tid & 31;
        for (int r = warp; r < 48; r += 8) {
            float v0 = sc[r*64 + lane], v1 = sc[r*64 + 32 + lane];
            float mx = fmaxf(v0, v1);
            #pragma unroll
            for (int o = 16; o > 0; o >>= 1)
                mx = fmaxf(mx, __shfl_xor_sync(0xffffffffu, mx, o));
            float e0 = expf(v0 - mx), e1 = expf(v1 - mx);
            float ss = e0 + e1;
            #pragma unroll
            for (int o = 16; o > 0; o >>= 1)
                ss += __shfl_xor_sync(0xffffffffu, ss, o);
            float inv = 1.f / ss;
            sc[r*64 + lane]      = e0 * inv;
            sc[r*64 + 32 + lane] = e1 * inv;
        }
    }
    __syncthreads();

    // 5) out: 192 threads, 4 t2-rows x 4 dims each
    if (tid < 192) {
        int dg = tid & 15, tg = (tid >> 4) & 3, h = tid >> 6;
        float acc[4][4] = {};
        const uint32_t* vhw = reinterpret_cast<const uint32_t*>(vh);
        #pragma unroll 4
        for (int s2 = 0; s2 < 32; s2++) {
            float2 pv[4], vv[4];
            #pragma unroll
            for (int i = 0; i < 4; i++) {
                pv[i] = *reinterpret_cast<const float2*>(&sc[(h*16 + tg*4 + i)*64 + s2*2]);
                uint32_t vw = vhw[(h*64 + dg*4 + i)*33 + s2];
                vv[i] = __bfloat1622float2(*reinterpret_cast<__nv_bfloat162*>(&vw));
            }
            #pragma unroll
            for (int i = 0; i < 4; i++)
                #pragma unroll
                for (int j = 0; j < 4; j++) {
                    acc[i][j] = fmaf(pv[i].x, vv[j].x, acc[i][j]);
                    acc[i][j] = fmaf(pv[i].y, vv[j].y, acc[i][j]);
                }
        }
        #pragma unroll
        for (int i = 0; i < 4; i++) {
            int t2 = tg*4 + i;
            size_t orow = ((size_t)(b*128 + wi*4 + (t2 >> 2)))*128 + wj*4 + (t2 & 3);
            size_t off = orow*192 + h*64 + dg*4;
            #pragma unroll
            for (int j = 0; j < 4; j += 2) {
                __nv_bfloat16 h0, l0, h1, l1;
                split_bf16(acc[i][j],   h0, l0);
                split_bf16(acc[i][j+1], h1, l1);
                __nv_bfloat162 hp, lp;
                hp.x = h0; hp.y = h1;
                lp.x = l0; lp.y = l1;
                *reinterpret_cast<__nv_bfloat162*>(Oh + off + j) = hp;
                *reinterpret_cast<__nv_bfloat162*>(Ol + off + j) = lp;
            }
        }
    }
}

// ---------------- launch ----------------------------------------------------
extern "C" void kernel_launch(void* const* d_in, const int* in_sizes, int n_in,
                              void* d_out, int out_size)
{
    const float* x       = (const float*)d_in[0];
    const float* n1g     = (const float*)d_in[1];
    const float* n1b     = (const float*)d_in[2];
    const float* proj_w  = (const float*)d_in[3];
    const float* proj_b  = (const float*)d_in[4];
    const float* qkv_w   = (const float*)d_in[5];
    const float* qkv_b   = (const float*)d_in[6];
    const float* apw     = (const float*)d_in[7];
    const float* apb     = (const float*)d_in[8];
    const float* n2g     = (const float*)d_in[9];
    const float* n2b     = (const float*)d_in[10];
    const float* w1      = (const float*)d_in[11];
    const float* b1      = (const float*)d_in[12];
    const float* w2      = (const float*)d_in[13];
    const float* b2      = (const float*)d_in[14];
    float* y = (float*)d_out;

    __nv_bfloat16 *xh, *xl, *qkvb, *oh, *ol, *ynh, *ynl, *hh, *hl;
    __nv_bfloat16 *wfh, *wfl, *wah, *wal, *w1h, *w1l, *w2h, *w2l;
    float *b768;
    cudaGetSymbolAddress((void**)&xh,  g_xh);
    cudaGetSymbolAddress((void**)&xl,  g_xl);
    cudaGetSymbolAddress((void**)&qkvb, g_qkvb);
    cudaGetSymbolAddress((void**)&oh,  g_oh);
    cudaGetSymbolAddress((void**)&ol,  g_ol);
    cudaGetSymbolAddress((void**)&ynh, g_ynh);
    cudaGetSymbolAddress((void**)&ynl, g_ynl);
    cudaGetSymbolAddress((void**)&hh,  g_hh);
    cudaGetSymbolAddress((void**)&hl,  g_hl);
    cudaGetSymbolAddress((void**)&wfh, g_wfh);
    cudaGetSymbolAddress((void**)&wfl, g_wfl);
    cudaGetSymbolAddress((void**)&wah, g_wah);
    cudaGetSymbolAddress((void**)&wal, g_wal);
    cudaGetSymbolAddress((void**)&w1h, g_w1h);
    cudaGetSymbolAddress((void**)&w1l, g_w1l);
    cudaGetSymbolAddress((void**)&w2h, g_w2h);
    cudaGetSymbolAddress((void**)&w2l, g_w2l);
    cudaGetSymbolAddress((void**)&b768, g_b768);

    static bool attr_done = false;
    if (!attr_done) {
        cudaFuncSetAttribute(attn_kernel,
            cudaFuncAttributeMaxDynamicSharedMemorySize, ATT_SMEM);
        cudaFuncSetAttribute(gemm_mma,
            cudaFuncAttributeMaxDynamicSharedMemorySize, GEMM_SMEM);
        attr_done = true;
    }

    // 0) merged weight conversions + bias concat
    conv_all_kernel<<<(406272 + 255) / 256, 256>>>(
        proj_w, qkv_w, apw, w1, w2, proj_b, qkv_b,
        wfh, wfl, wah, wal, w1h, w1l, w2h, w2l, b768);
    // 1) LN1 -> bf16 hi/lo (window-major rows)
    ln96b_kernel<<<NPIX/8, 256>>>(x, n1g, n1b, xh, xl);
    // 2) fused proj+qkv GEMM: tile0 -> pooled y, tiles1-3 -> qkv bf16
    gemm_mma<<<dim3(4, NPIX/128), 256, GEMM_SMEM>>>(
        xh, xl, wfh, wfl, 96, 768, 3, b768, y, qkvb, nullptr, nullptr);
    // 3) windowed attention -> O (bf16 hi/lo)
    attn_kernel<<<NWIN, 256, ATT_SMEM>>>(qkvb, oh, ol);
    // 4) attn-proj GEMM: y += O @ apw + apb
    gemm_mma<<<dim3(1, NPOOL/128), 256, GEMM_SMEM>>>(
        oh, ol, wah, wal, 192, 192, 2, apb, y, nullptr, nullptr, y);
    // 5) LN2 -> bf16 hi/lo
    ln192b_kernel<<<NPOOL/8, 256>>>(y, n2g, n2b, ynh, ynl);
    // 6) mlp1 GEMM + gelu -> h (bf16 hi/lo)
    gemm_mma<<<dim3(4, NPOOL/128), 256, GEMM_SMEM>>>(
        ynh, ynl, w1h, w1l, 192, 768, 1, b1, nullptr, hh, hl, nullptr);
    // 7) mlp2 GEMM + residual add -> y (d_out)
    gemm_mma<<<dim3(1, NPOOL/128), 256, GEMM_SMEM>>>(
        hh, hl, w2h, w2l, 768, 192, 2, b2, y, nullptr, nullptr, y);
}

// round 8
// speedup vs baseline: 2.2735x; 1.0092x over previous
#include <cuda_runtime.h>
#include <cuda_bf16.h>
#include <cstdint>
#include <math.h>

// ===========================================================================
// MultiScaleBlock (sm_103 PTX, HMMA mma.sync path).
// Window-major pixel permutation: row = (((b*32+wi)*32+wj)*16 + t2)*4 + dq.
// Fused proj+qkv GEMM with maxpool fused in epilogue.
// Precision tiers: proj/attn-proj/mlp GEMMs bf16x3 (hi/lo); qkv tiles bf16x1.
// Attention: bf16x2-packed smem + 4x4 register blocking, all heads parallel.
// ===========================================================================

#define NPIX   (4*256*256)     // 262144
#define NPOOL  (4*128*128)     // 65536
#define NWIN   (4*32*32)       // 4096

// ---------------- scratch (device globals) ----------------------------------
__device__ __nv_bfloat16 g_xh [(size_t)NPIX  * 96];
__device__ __nv_bfloat16 g_xl [(size_t)NPIX  * 96];
__device__ __nv_bfloat16 g_qkvb[(size_t)NPIX * 576];     // bf16 qkv, window-major
__device__ __nv_bfloat16 g_oh [(size_t)NPOOL * 192];
__device__ __nv_bfloat16 g_ol [(size_t)NPOOL * 192];
__device__ __nv_bfloat16 g_ynh[(size_t)NPOOL * 192];
__device__ __nv_bfloat16 g_ynl[(size_t)NPOOL * 192];
__device__ __nv_bfloat16 g_hh [(size_t)NPOOL * 768];
__device__ __nv_bfloat16 g_hl [(size_t)NPOOL * 768];
// weights [N][K] bf16 hi/lo (transposed); proj+qkv fused into 768 rows
__device__ __nv_bfloat16 g_wfh[768*96],  g_wfl[768*96];
__device__ __nv_bfloat16 g_wah[192*192], g_wal[192*192];
__device__ __nv_bfloat16 g_w1h[768*192], g_w1l[768*192];
__device__ __nv_bfloat16 g_w2h[192*768], g_w2l[192*768];
__device__ float         g_b768[768];

// ---------------- helpers ---------------------------------------------------
__device__ __forceinline__ uint32_t smem_u32(const void* p) {
    uint32_t a;
    asm("{ .reg .u64 t; cvta.to.shared.u64 t, %1; cvt.u32.u64 %0, t; }"
        : "=r"(a) : "l"(p));
    return a;
}
__device__ __forceinline__ void cp16(uint32_t s, const void* g) {
    asm volatile("cp.async.ca.shared.global [%0], [%1], 16;"
                 :: "r"(s), "l"(g) : "memory");
}
__device__ __forceinline__ void cp_commit() {
    asm volatile("cp.async.commit_group;" ::: "memory");
}
template<int N>
__device__ __forceinline__ void cp_wait() {
    asm volatile("cp.async.wait_group %0;" :: "n"(N) : "memory");
}
__device__ __forceinline__ void ldsm4(uint32_t* r, uint32_t a) {
    asm volatile("ldmatrix.sync.aligned.m8n8.x4.shared.b16 {%0,%1,%2,%3}, [%4];"
        : "=r"(r[0]), "=r"(r[1]), "=r"(r[2]), "=r"(r[3]) : "r"(a));
}
__device__ __forceinline__ void mma_bf16(float* d, const uint32_t* a,
                                         uint32_t b0, uint32_t b1) {
    asm volatile(
        "mma.sync.aligned.m16n8k16.row.col.f32.bf16.bf16.f32 "
        "{%0,%1,%2,%3}, {%4,%5,%6,%7}, {%8,%9}, {%0,%1,%2,%3};"
        : "+f"(d[0]), "+f"(d[1]), "+f"(d[2]), "+f"(d[3])
        : "r"(a[0]), "r"(a[1]), "r"(a[2]), "r"(a[3]), "r"(b0), "r"(b1));
}
__device__ __forceinline__ void split_bf16(float v, __nv_bfloat16& h, __nv_bfloat16& l) {
    h = __float2bfloat16(v);
    l = __float2bfloat16(v - __bfloat162float(h));
}
__device__ __forceinline__ float gelu_exact(float v) {
    return 0.5f * v * (1.0f + erff(v * 0.70710678118654752f));
}
// window-major quad index -> standard pooled row
__device__ __forceinline__ size_t quad_to_prow(size_t g) {
    int t2 = (int)(g & 15);
    int wj = (int)((g >> 4) & 31);
    int wi = (int)((g >> 9) & 31);
    int b  = (int)(g >> 14);
    return ((size_t)(b * 128 + wi * 4 + (t2 >> 2))) * 128 + wj * 4 + (t2 & 3);
}

// ---------------- HMMA GEMM, BM=128 BN=192 BK=32, 3-stage -------------------
// x3 CTAs: hi/lo x3-product (2^-17); x1 CTAs (qkv tiles): hi-only (bf16).
#define LDA     40                         // BK + 8 (half-words)
#define SA_HI   0
#define SA_LO   (128*LDA*2)                // 10240
#define SB_HI   (2*128*LDA*2)              // 20480
#define SB_LO   (SB_HI + 192*LDA*2)        // 35840
#define STAGE_B (SB_LO + 192*LDA*2)        // 51200
#define GEMM_SMEM (3*STAGE_B)              // 153600

__global__ __launch_bounds__(256, 1) void gemm_mma(
    const __nv_bfloat16* __restrict__ Ah, const __nv_bfloat16* __restrict__ Al,
    const __nv_bfloat16* __restrict__ Bh, const __nv_bfloat16* __restrict__ Bl,
    int K, int N, int epi,
    const float* __restrict__ bias,
    float* __restrict__ Cf,
    __nv_bfloat16* __restrict__ Ch, __nv_bfloat16* __restrict__ Cl,
    const float* __restrict__ addsrc)
{
    extern __shared__ char smem[];
    const uint32_t sb = smem_u32(smem);
    const int tid = threadIdx.x, lane = tid & 31, warp = tid >> 5;
    const int wm = (warp >> 1) * 32;           // 4 warps in M
    const int wn = (warp & 1) * 96;            // 2 warps in N
    const size_t bm = (size_t)blockIdx.y * 128;
    const size_t bn = (size_t)blockIdx.x * 192;
    const int C = K >> 5;
    const bool x3 = !(epi == 3 && blockIdx.x != 0);   // qkv tiles: bf16x1

    const __nv_bfloat16* AhB = Ah + bm * K;
    const __nv_bfloat16* AlB = Al + bm * K;
    const __nv_bfloat16* BhB = Bh + bn * K;
    const __nv_bfloat16* BlB = Bl + bn * K;

    float acc[2][12][4];
    #pragma unroll
    for (int i = 0; i < 2; i++)
        #pragma unroll
        for (int j = 0; j < 12; j++)
            #pragma unroll
            for (int q = 0; q < 4; q++) acc[i][j][q] = 0.f;

    auto load_stage = [&](int s, int c) {
        const uint32_t st = sb + (uint32_t)s * STAGE_B;
        const size_t k0 = (size_t)c * 32;
        #pragma unroll
        for (int i = tid; i < 512; i += 256) {       // A: 128 rows x 4 chunks
            int r = i >> 2, q = i & 3;
            uint32_t d = st + (uint32_t)(r * LDA + q * 8) * 2;
            size_t go = (size_t)r * K + k0 + q * 8;
            cp16(d + SA_HI, AhB + go);
            if (x3) cp16(d + SA_LO, AlB + go);
        }
        #pragma unroll
        for (int i = tid; i < 768; i += 256) {       // B: 192 rows x 4 chunks
            int r = i >> 2, q = i & 3;
            uint32_t d = st + (uint32_t)(r * LDA + q * 8) * 2;
            size_t go = (size_t)r * K + k0 + q * 8;
            cp16(d + SB_HI, BhB + go);
            if (x3) cp16(d + SB_LO, BlB + go);
        }
        cp_commit();
    };

    auto compute_stage = [&](int s) {
        const uint32_t st = sb + (uint32_t)s * STAGE_B;
        #pragma unroll
        for (int k16 = 0; k16 < 2; k16++) {
            uint32_t ah[2][4], al[2][4];
            #pragma unroll
            for (int mi = 0; mi < 2; mi++) {
                int row = wm + mi * 16 + (lane & 15);
                int col = k16 * 16 + (lane >> 4) * 8;
                uint32_t ad = st + (uint32_t)(row * LDA + col) * 2;
                ldsm4(ah[mi], ad + SA_HI);
                if (x3) ldsm4(al[mi], ad + SA_LO);
            }
            #pragma unroll
            for (int ng = 0; ng < 6; ng++) {
                uint32_t bh[4], bl[4];
                int nr = wn + ng * 16 + (lane & 7) + ((lane >> 4) & 1) * 8;
                int bc = k16 * 16 + ((lane >> 3) & 1) * 8;
                uint32_t bd = st + (uint32_t)(nr * LDA + bc) * 2;
                ldsm4(bh, bd + SB_HI);
                if (x3) ldsm4(bl, bd + SB_LO);
                #pragma unroll
                for (int mi = 0; mi < 2; mi++) {
                    #pragma unroll
                    for (int sub = 0; sub < 2; sub++) {
                        float* d = acc[mi][ng * 2 + sub];
                        mma_bf16(d, ah[mi], bh[2*sub], bh[2*sub+1]);
                        if (x3) {
                            mma_bf16(d, ah[mi], bl[2*sub], bl[2*sub+1]);
                            mma_bf16(d, al[mi], bh[2*sub], bh[2*sub+1]);
                        }
                    }
                }
            }
        }
    };

    // ---- 3-stage pipeline ----
    load_stage(0, 0);
    load_stage(1, 1);
    for (int c = 0; c < C; c++) {
        if (c + 1 < C) { cp_wait<1>(); } else { cp_wait<0>(); }
        __syncthreads();
        if (c + 2 < C) load_stage((c + 2) % 3, c + 2);
        compute_stage(c % 3);
        __syncthreads();
    }

    // ---- epilogue ----
    #pragma unroll
    for (int mi = 0; mi < 2; mi++) {
        #pragma unroll
        for (int nj = 0; nj < 12; nj++) {
            size_t row0 = bm + wm + mi * 16 + (lane >> 2);
            size_t col  = bn + wn + nj * 8 + 2 * (lane & 3);
            float b0 = bias[col], b1 = bias[col + 1];
            float v00 = acc[mi][nj][0] + b0, v01 = acc[mi][nj][1] + b1;
            float v10 = acc[mi][nj][2] + b0, v11 = acc[mi][nj][3] + b1;
            if (epi == 1) {
                v00 = gelu_exact(v00); v01 = gelu_exact(v01);
                v10 = gelu_exact(v10); v11 = gelu_exact(v11);
                __nv_bfloat16 h, l;
                __nv_bfloat162 hp, lp;
                split_bf16(v00, h, l); hp.x = h; lp.x = l;
                split_bf16(v01, h, l); hp.y = h; lp.y = l;
                *reinterpret_cast<__nv_bfloat162*>(Ch + row0 * N + col) = hp;
                *reinterpret_cast<__nv_bfloat162*>(Cl + row0 * N + col) = lp;
                split_bf16(v10, h, l); hp.x = h; lp.x = l;
                split_bf16(v11, h, l); hp.y = h; lp.y = l;
                *reinterpret_cast<__nv_bfloat162*>(Ch + (row0 + 8) * N + col) = hp;
                *reinterpret_cast<__nv_bfloat162*>(Cl + (row0 + 8) * N + col) = lp;
            } else if (epi == 2) {
                const float2 a0 = *reinterpret_cast<const float2*>(addsrc + row0 * N + col);
                const float2 a1 = *reinterpret_cast<const float2*>(addsrc + (row0 + 8) * N + col);
                *reinterpret_cast<float2*>(Cf + row0 * N + col)       = make_float2(v00 + a0.x, v01 + a0.y);
                *reinterpret_cast<float2*>(Cf + (row0 + 8) * N + col) = make_float2(v10 + a1.x, v11 + a1.y);
            } else {  // epi == 3
                if (bn == 0) {
                    float p00 = fmaxf(v00, __shfl_xor_sync(0xffffffffu, v00, 4));
                    p00 = fmaxf(p00, __shfl_xor_sync(0xffffffffu, p00, 8));
                    float p01 = fmaxf(v01, __shfl_xor_sync(0xffffffffu, v01, 4));
                    p01 = fmaxf(p01, __shfl_xor_sync(0xffffffffu, p01, 8));
                    float p10 = fmaxf(v10, __shfl_xor_sync(0xffffffffu, v10, 4));
                    p10 = fmaxf(p10, __shfl_xor_sync(0xffffffffu, p10, 8));
                    float p11 = fmaxf(v11, __shfl_xor_sync(0xffffffffu, v11, 4));
                    p11 = fmaxf(p11, __shfl_xor_sync(0xffffffffu, p11, 8));
                    if ((lane & 12) == 0) {
                        size_t pr0 = quad_to_prow(row0 >> 2);
                        size_t pr1 = quad_to_prow((row0 + 8) >> 2);
                        *reinterpret_cast<float2*>(Cf + pr0 * 192 + col) = make_float2(p00, p01);
                        *reinterpret_cast<float2*>(Cf + pr1 * 192 + col) = make_float2(p10, p11);
                    }
                } else {
                    size_t qc = col - 192;
                    __nv_bfloat162 p0, p1;
                    p0.x = __float2bfloat16(v00); p0.y = __float2bfloat16(v01);
                    p1.x = __float2bfloat16(v10); p1.y = __float2bfloat16(v11);
                    *reinterpret_cast<__nv_bfloat162*>(Ch + row0 * 576 + qc)       = p0;
                    *reinterpret_cast<__nv_bfloat162*>(Ch + (row0 + 8) * 576 + qc) = p1;
                }
            }
        }
    }
}

// ---------------- LN1 -> bf16 hi/lo, window-major permuted rows -------------
__global__ __launch_bounds__(256) void ln96b_kernel(
    const float* __restrict__ x, const float* __restrict__ g,
    const float* __restrict__ bb,
    __nv_bfloat16* __restrict__ hi, __nv_bfloat16* __restrict__ lo)
{
    int row  = blockIdx.x * 8 + (threadIdx.x >> 5);   // source pixel
    int lane = threadIdx.x & 31;
    const float* p = x + (size_t)row * 96;
    float v0 = p[lane], v1 = p[lane+32], v2 = p[lane+64];
    float s = v0 + v1 + v2;
    #pragma unroll
    for (int o = 16; o > 0; o >>= 1) s += __shfl_xor_sync(0xffffffffu, s, o);
    float mean = s * (1.0f/96.0f);
    float d0 = v0-mean, d1 = v1-mean, d2 = v2-mean;
    float vs = d0*d0 + d1*d1 + d2*d2;
    #pragma unroll
    for (int o = 16; o > 0; o >>= 1) vs += __shfl_xor_sync(0xffffffffu, vs, o);
    float inv = rsqrtf(vs * (1.0f/96.0f) + 1e-6f);
    float y0 = d0*inv*g[lane]    + bb[lane];
    float y1 = d1*inv*g[lane+32] + bb[lane+32];
    float y2 = d2*inv*g[lane+64] + bb[lane+64];
    int wpix = row & 255, hpix = (row >> 8) & 255, b = row >> 16;
    int wi = hpix >> 3, r = hpix & 7, wj = wpix >> 3, c = wpix & 7;
    int t2 = (r >> 1) * 4 + (c >> 1);
    int dq = (r & 1) * 2 + (c & 1);
    size_t wrow = ((((size_t)b * 32 + wi) * 32 + wj) * 16 + t2) * 4 + dq;
    __nv_bfloat16* ph = hi + wrow * 96;
    __nv_bfloat16* pl = lo + wrow * 96;
    __nv_bfloat16 h, l;
    split_bf16(y0, h, l); ph[lane]    = h; pl[lane]    = l;
    split_bf16(y1, h, l); ph[lane+32] = h; pl[lane+32] = l;
    split_bf16(y2, h, l); ph[lane+64] = h; pl[lane+64] = l;
}

__global__ __launch_bounds__(256) void ln192b_kernel(
    const float* __restrict__ x, const float* __restrict__ g,
    const float* __restrict__ bb,
    __nv_bfloat16* __restrict__ hi, __nv_bfloat16* __restrict__ lo)
{
    int row  = blockIdx.x * 8 + (threadIdx.x >> 5);
    int lane = threadIdx.x & 31;
    const float* p = x + (size_t)row * 192;
    float v[6];
    float s = 0.f;
    #pragma unroll
    for (int i = 0; i < 6; i++) { v[i] = p[lane + 32*i]; s += v[i]; }
    #pragma unroll
    for (int o = 16; o > 0; o >>= 1) s += __shfl_xor_sync(0xffffffffu, s, o);
    float mean = s * (1.0f/192.0f);
    float vs = 0.f;
    #pragma unroll
    for (int i = 0; i < 6; i++) { v[i] -= mean; vs += v[i]*v[i]; }
    #pragma unroll
    for (int o = 16; o > 0; o >>= 1) vs += __shfl_xor_sync(0xffffffffu, vs, o);
    float inv = rsqrtf(vs * (1.0f/192.0f) + 1e-6f);
    __nv_bfloat16* ph = hi + (size_t)row * 192;
    __nv_bfloat16* pl = lo + (size_t)row * 192;
    #pragma unroll
    for (int i = 0; i < 6; i++) {
        float y = v[i]*inv*g[lane + 32*i] + bb[lane + 32*i];
        __nv_bfloat16 h, l;
        split_bf16(y, h, l);
        ph[lane + 32*i] = h; pl[lane + 32*i] = l;
    }
}

// ---------------- merged weight conversion + bias concat --------------------
__global__ __launch_bounds__(256) void conv_all_kernel(
    const float* __restrict__ proj_w, const float* __restrict__ qkv_w,
    const float* __restrict__ apw, const float* __restrict__ w1,
    const float* __restrict__ w2,
    const float* __restrict__ proj_b, const float* __restrict__ qkv_b,
    __nv_bfloat16* __restrict__ wfh, __nv_bfloat16* __restrict__ wfl,
    __nv_bfloat16* __restrict__ wah, __nv_bfloat16* __restrict__ wal,
    __nv_bfloat16* __restrict__ w1h, __nv_bfloat16* __restrict__ w1l,
    __nv_bfloat16* __restrict__ w2h, __nv_bfloat16* __restrict__ w2l,
    float* __restrict__ b768)
{
    int i = blockIdx.x * 256 + threadIdx.x;
    const float* W; __nv_bfloat16 *H, *L;
    int K, N, j;
    if (i < 18432)        { W = proj_w; H = wfh;            L = wfl;            K = 96;  N = 192; j = i; }
    else if (i < 73728)   { W = qkv_w;  H = wfh + 18432;    L = wfl + 18432;    K = 96;  N = 576; j = i - 18432; }
    else if (i < 110592)  { W = apw;    H = wah;            L = wal;            K = 192; N = 192; j = i - 73728; }
    else if (i < 258048)  { W = w1;     H = w1h;            L = w1l;            K = 192; N = 768; j = i - 110592; }
    else if (i < 405504)  { W = w2;     H = w2h;            L = w2l;            K = 768; N = 192; j = i - 258048; }
    else if (i < 406272)  { j = i - 405504; b768[j] = (j < 192) ? proj_b[j] : qkv_b[j - 192]; return; }
    else return;
    int n = j / K, k = j % K;
    float v = W[(size_t)k * N + n];
    __nv_bfloat16 h, l;
    split_bf16(v, h, l);
    H[j] = h; L[j] = l;
}

// ---------------- windowed attention: packed bf16x2, 4x4 reg blocking -------
#define ATT_SMEM 70912

__global__ __launch_bounds__(256, 2) void attn_kernel(
    const __nv_bfloat16* __restrict__ qkv,
    __nv_bfloat16* __restrict__ Oh, __nv_bfloat16* __restrict__ Ol)
{
    extern __shared__ float sm[];
    uint32_t* qp = reinterpret_cast<uint32_t*>(sm);                    // [16][100]
    uint32_t* kh = qp + 1600;                                          // [3][64][35]
    __nv_bfloat16* vh = reinterpret_cast<__nv_bfloat16*>(kh + 6720);   // [3][64][66]
    float* sc = sm + 14656;                                            // [3][16][64]

    int w = blockIdx.x;
    int b = w >> 10, wi = (w >> 5) & 31, wj = w & 31;
    int tid = threadIdx.x;
    const uint32_t* qk = reinterpret_cast<const uint32_t*>(qkv + (size_t)w * 64 * 576);

    // 1) pooled q (bf16-exact max), packed bf16x2
    for (int i = tid; i < 16*96; i += 256) {
        int t2 = i / 96, c2 = i % 96;
        float m0 = -1e30f, m1 = -1e30f;
        #pragma unroll
        for (int dq = 0; dq < 4; dq++) {
            uint32_t wd = qk[(t2*4 + dq)*288 + c2];
            __nv_bfloat162 v = *reinterpret_cast<__nv_bfloat162*>(&wd);
            m0 = fmaxf(m0, __bfloat162float(v.x));
            m1 = fmaxf(m1, __bfloat162float(v.y));
        }
        __nv_bfloat162 r;
        r.x = __float2bfloat16(m0); r.y = __float2bfloat16(m1);
        qp[t2*100 + c2] = *reinterpret_cast<uint32_t*>(&r);
    }
    // 2) k packed rows; v transposed to [d][s] bf16
    for (int i = tid; i < 3*64*32; i += 256) {
        int d2 = i & 31, s = (i >> 5) & 63, h = i >> 11;
        kh[(h*64 + s)*35 + d2] = qk[s*288 + 96 + h*32 + d2];
        uint32_t vw = qk[s*288 + 192 + h*32 + d2];
        __nv_bfloat162 vv = *reinterpret_cast<__nv_bfloat162*>(&vw);
        vh[(h*64 + d2*2    )*66 + s] = vv.x;
        vh[(h*64 + d2*2 + 1)*66 + s] = vv.y;
    }
    __syncthreads();

    // 3) scores: 192 threads, 4 t2-rows x 4 keys each
    if (tid < 192) {
        int sg = tid & 15, tg = (tid >> 4) & 3, h = tid >> 6;
        float acc[4][4] = {};
        #pragma unroll 4
        for (int d2 = 0; d2 < 32; d2++) {
            float2 qv[4], kv[4];
            #pragma unroll
            for (int i = 0; i < 4; i++) {
                uint32_t qw = qp[(tg*4 + i)*100 + h*32 + d2];
                qv[i] = __bfloat1622float2(*reinterpret_cast<__nv_bfloat162*>(&qw));
                uint32_t kw = kh[(h*64 + sg*4 + i)*35 + d2];
                kv[i] = __bfloat1622float2(*reinterpret_cast<__nv_bfloat162*>(&kw));
            }
            #pragma unroll
            for (int i = 0; i < 4; i++)
                #pragma unroll
                for (int j = 0; j < 4; j++) {
                    acc[i][j] = fmaf(qv[i].x, kv[j].x, acc[i][j]);
                    acc[i][j] = fmaf(qv[i].y, kv[j].y, acc[i][j]);
                }
        }
        #pragma unroll
        for (int i = 0; i < 4; i++)
            #pragma unroll
            for (int j = 0; j < 4; j++)
                sc[(h*16 + tg*4 + i)*64 + sg*4 + j] = acc[i][j] * 0.125f;
    }
    __syncthreads();

    // 4) softmax: 48 rows over 8 warps
    {
        int warp = tid >> 5, lane = tid & 31;
        for (int r = warp; r < 48; r += 8) {
            float v0 = sc[r*64 + lane], v1 = sc[r*64 + 32 + lane];
            float mx = fmaxf(v0, v1);
            #pragma unroll
            for (int o = 16; o > 0; o >>= 1)
                mx = fmaxf(mx, __shfl_xor_sync(0xffffffffu, mx, o));
            float e0 = expf(v0 - mx), e1 = expf(v1 - mx);
            float ss = e0 + e1;
            #pragma unroll
            for (int o = 16; o > 0; o >>= 1)
                ss += __shfl_xor_sync(0xffffffffu, ss, o);
            float inv = 1.f / ss;
            sc[r*64 + lane]      = e0 * inv;
            sc[r*64 + 32 + lane] = e1 * inv;
        }
    }
    __syncthreads();

    // 5) out: 192 threads, 4 t2-rows x 4 dims each
    if (tid < 192) {
        int dg = tid & 15, tg = (tid >> 4) & 3, h = tid >> 6;
        float acc[4][4] = {};
        const uint32_t* vhw = reinterpret_cast<const uint32_t*>(vh);
        #pragma unroll 4
        for (int s2 = 0; s2 < 32; s2++) {
            float2 pv[4], vv[4];
            #pragma unroll
            for (int i = 0; i < 4; i++) {
                pv[i] = *reinterpret_cast<const float2*>(&sc[(h*16 + tg*4 + i)*64 + s2*2]);
                uint32_t vw = vhw[(h*64 + dg*4 + i)*33 + s2];
                vv[i] = __bfloat1622float2(*reinterpret_cast<__nv_bfloat162*>(&vw));
            }
            #pragma unroll
            for (int i = 0; i < 4; i++)
                #pragma unroll
                for (int j = 0; j < 4; j++) {
                    acc[i][j] = fmaf(pv[i].x, vv[j].x, acc[i][j]);
                    acc[i][j] = fmaf(pv[i].y, vv[j].y, acc[i][j]);
                }
        }
        #pragma unroll
        for (int i = 0; i < 4; i++) {
            int t2 = tg*4 + i;
            size_t orow = ((size_t)(b*128 + wi*4 + (t2 >> 2)))*128 + wj*4 + (t2 & 3);
            size_t off = orow*192 + h*64 + dg*4;
            #pragma unroll
            for (int j = 0; j < 4; j += 2) {
                __nv_bfloat16 h0, l0, h1, l1;
                split_bf16(acc[i][j],   h0, l0);
                split_bf16(acc[i][j+1], h1, l1);
                __nv_bfloat162 hp, lp;
                hp.x = h0; hp.y = h1;
                lp.x = l0; lp.y = l1;
                *reinterpret_cast<__nv_bfloat162*>(Oh + off + j) = hp;
                *reinterpret_cast<__nv_bfloat162*>(Ol + off + j) = lp;
            }
        }
    }
}

// ---------------- launch ----------------------------------------------------
extern "C" void kernel_launch(void* const* d_in, const int* in_sizes, int n_in,
                              void* d_out, int out_size)
{
    const float* x       = (const float*)d_in[0];
    const float* n1g     = (const float*)d_in[1];
    const float* n1b     = (const float*)d_in[2];
    const float* proj_w  = (const float*)d_in[3];
    const float* proj_b  = (const float*)d_in[4];
    const float* qkv_w   = (const float*)d_in[5];
    const float* qkv_b   = (const float*)d_in[6];
    const float* apw     = (const float*)d_in[7];
    const float* apb     = (const float*)d_in[8];
    const float* n2g     = (const float*)d_in[9];
    const float* n2b     = (const float*)d_in[10];
    const float* w1      = (const float*)d_in[11];
    const float* b1      = (const float*)d_in[12];
    const float* w2      = (const float*)d_in[13];
    const float* b2      = (const float*)d_in[14];
    float* y = (float*)d_out;

    __nv_bfloat16 *xh, *xl, *qkvb, *oh, *ol, *ynh, *ynl, *hh, *hl;
    __nv_bfloat16 *wfh, *wfl, *wah, *wal, *w1h, *w1l, *w2h, *w2l;
    float *b768;
    cudaGetSymbolAddress((void**)&xh,  g_xh);
    cudaGetSymbolAddress((void**)&xl,  g_xl);
    cudaGetSymbolAddress((void**)&qkvb, g_qkvb);
    cudaGetSymbolAddress((void**)&oh,  g_oh);
    cudaGetSymbolAddress((void**)&ol,  g_ol);
    cudaGetSymbolAddress((void**)&ynh, g_ynh);
    cudaGetSymbolAddress((void**)&ynl, g_ynl);
    cudaGetSymbolAddress((void**)&hh,  g_hh);
    cudaGetSymbolAddress((void**)&hl,  g_hl);
    cudaGetSymbolAddress((void**)&wfh, g_wfh);
    cudaGetSymbolAddress((void**)&wfl, g_wfl);
    cudaGetSymbolAddress((void**)&wah, g_wah);
    cudaGetSymbolAddress((void**)&wal, g_wal);
    cudaGetSymbolAddress((void**)&w1h, g_w1h);
    cudaGetSymbolAddress((void**)&w1l, g_w1l);
    cudaGetSymbolAddress((void**)&w2h, g_w2h);
    cudaGetSymbolAddress((void**)&w2l, g_w2l);
    cudaGetSymbolAddress((void**)&b768, g_b768);

    static bool attr_done = false;
    if (!attr_done) {
        cudaFuncSetAttribute(attn_kernel,
            cudaFuncAttributeMaxDynamicSharedMemorySize, ATT_SMEM);
        cudaFuncSetAttribute(gemm_mma,
            cudaFuncAttributeMaxDynamicSharedMemorySize, GEMM_SMEM);
        attr_done = true;
    }

    // 0) merged weight conversions + bias concat
    conv_all_kernel<<<(406272 + 255) / 256, 256>>>(
        proj_w, qkv_w, apw, w1, w2, proj_b, qkv_b,
        wfh, wfl, wah, wal, w1h, w1l, w2h, w2l, b768);
    // 1) LN1 -> bf16 hi/lo (window-major rows)
    ln96b_kernel<<<NPIX/8, 256>>>(x, n1g, n1b, xh, xl);
    // 2) fused proj+qkv GEMM: tile0 (x3) -> pooled y, tiles1-3 (x1) -> qkv bf16
    gemm_mma<<<dim3(4, NPIX/128), 256, GEMM_SMEM>>>(
        xh, xl, wfh, wfl, 96, 768, 3, b768, y, qkvb, nullptr, nullptr);
    // 3) windowed attention -> O (bf16 hi/lo)
    attn_kernel<<<NWIN, 256, ATT_SMEM>>>(qkvb, oh, ol);
    // 4) attn-proj GEMM: y += O @ apw + apb
    gemm_mma<<<dim3(1, NPOOL/128), 256, GEMM_SMEM>>>(
        oh, ol, wah, wal, 192, 192, 2, apb, y, nullptr, nullptr, y);
    // 5) LN2 -> bf16 hi/lo
    ln192b_kernel<<<NPOOL/8, 256>>>(y, n2g, n2b, ynh, ynl);
    // 6) mlp1 GEMM + gelu -> h (bf16 hi/lo)
    gemm_mma<<<dim3(4, NPOOL/128), 256, GEMM_SMEM>>>(
        ynh, ynl, w1h, w1l, 192, 768, 1, b1, nullptr, hh, hl, nullptr);
    // 7) mlp2 GEMM + residual add -> y (d_out)
    gemm_mma<<<dim3(1, NPOOL/128), 256, GEMM_SMEM>>>(
        hh, hl, w2h, w2l, 768, 192, 2, b2, y, nullptr, nullptr, y);
}